// round 7
// baseline (speedup 1.0000x reference)
#include <cuda_runtime.h>
#include <math.h>
#include <stdint.h>

#define NB   8
#define NN   256
#define NH   4
#define HD   64
#define FIN  256
#define ALPHA 0.2f

// ---------------- scratch (__device__ globals; no allocs allowed) ----------
__device__ float g_Wh [NB*NH*NN*HD];
__device__ float g_si2[NB*NH*NN*HD];   // si + ba1 + 0.6*(ei@We)
__device__ float g_sj2[NB*NH*NN*HD];   // sj + 0.6*(ej@We)
__device__ float g_ei [NB*NH*NN*HD];
__device__ float g_ej [NB*NH*NN*HD];
__device__ float g_concat[NB*NN*FIN];

// ---------------- packed helpers -------------------------------------------
__device__ __forceinline__ unsigned long long pack2(float v) {
    unsigned long long r; unsigned u = __float_as_uint(v);
    asm("mov.b64 %0, {%1, %1};" : "=l"(r) : "r"(u));
    return r;
}
__device__ __forceinline__ void fma2(unsigned long long& d,
                                     unsigned long long a, unsigned long long b) {
    asm("fma.rn.f32x2 %0, %1, %2, %0;" : "+l"(d) : "l"(a), "l"(b));
}
__device__ __forceinline__ void unpack2(unsigned long long v, float& lo, float& hi) {
    unsigned a, b;
    asm("mov.b64 {%0, %1}, %2;" : "=r"(a), "=r"(b) : "l"(v));
    lo = __uint_as_float(a); hi = __uint_as_float(b);
}
__device__ __forceinline__ uint32_t packbf(float lo, float hi) {   // low half = lo
    uint32_t r;
    asm("cvt.rn.bf16x2.f32 %0, %1, %2;" : "=r"(r) : "f"(hi), "f"(lo));
    return r;
}
__device__ __forceinline__ uint32_t hadd2(uint32_t a, uint32_t b) {
    uint32_t r;
    asm("add.rn.bf16x2 %0, %1, %2;" : "=r"(r) : "r"(a), "r"(b));
    return r;
}
__device__ __forceinline__ uint32_t habs2(uint32_t a) { return a & 0x7FFF7FFFu; }

__device__ __forceinline__ void mma16816(float* c, uint32_t a0, uint32_t a1,
                                         uint32_t a2, uint32_t a3,
                                         uint32_t b0, uint32_t b1) {
    asm volatile("mma.sync.aligned.m16n8k16.row.col.f32.bf16.bf16.f32 "
                 "{%0,%1,%2,%3}, {%4,%5,%6,%7}, {%8,%9}, {%0,%1,%2,%3};"
                 : "+f"(c[0]), "+f"(c[1]), "+f"(c[2]), "+f"(c[3])
                 : "r"(a0), "r"(a1), "r"(a2), "r"(a3), "r"(b0), "r"(b1));
}

// ---------------------------------------------------------------------------
// Kernel 1: NT=4, high occupancy, scalar FFMA.
// ---------------------------------------------------------------------------
__global__ __launch_bounds__(256) void k1_proj(
    const float* __restrict__ hin, const float* __restrict__ W,
    const float* __restrict__ We1, const float* __restrict__ be1,
    const float* __restrict__ Wa1, const float* __restrict__ ba1)
{
    const int NT = 4;
    int b  = blockIdx.x >> 6;
    int n0 = (blockIdx.x & 63) * NT;
    int tid = threadIdx.x;
    int head = tid >> 6, d = tid & 63;

    __shared__ float hs [NT][FIN];
    __shared__ float whs[NT][FIN];
    __shared__ float eis[NT][FIN];
    __shared__ float ejs[NT][FIN];

    for (int nn = 0; nn < NT; ++nn)
        hs[nn][tid] = hin[((size_t)(b*NN + n0 + nn))*FIN + tid];
    __syncthreads();

    float accW[NT], accE1[NT], accE2[NT];
#pragma unroll
    for (int nn = 0; nn < NT; ++nn) { accW[nn]=0.f; accE1[nn]=0.f; accE2[nn]=0.f; }

#pragma unroll 4
    for (int f = 0; f < FIN; ++f) {
        float wv = W  [((size_t)head*FIN + f)*HD + d];
        float w1 = We1[((size_t)head*2*FIN + f)*HD + d];
        float w2 = We1[((size_t)head*2*FIN + FIN + f)*HD + d];
#pragma unroll
        for (int nn = 0; nn < NT; ++nn) {
            float hv = hs[nn][f];
            accW[nn]  = fmaf(hv, wv, accW[nn]);
            accE1[nn] = fmaf(hv, w1, accE1[nn]);
            accE2[nn] = fmaf(hv, w2, accE2[nn]);
        }
    }

    float bei = be1[head*HD + d];
#pragma unroll
    for (int nn = 0; nn < NT; ++nn) {
        size_t base = ((size_t)(b*NH + head)*NN + (n0 + nn))*HD + d;
        float e1 = accE1[nn] + bei;
        g_Wh[base] = accW[nn];
        g_ei[base] = e1;
        g_ej[base] = accE2[nn];
        whs[nn][tid] = accW[nn];
        eis[nn][tid] = e1;
        ejs[nn][tid] = accE2[nn];
    }
    __syncthreads();

    float accSi[NT], accSj[NT], accP[NT], accQ[NT];
#pragma unroll
    for (int nn = 0; nn < NT; ++nn) { accSi[nn]=0.f; accSj[nn]=0.f; accP[nn]=0.f; accQ[nn]=0.f; }

    for (int k0 = 0; k0 < HD; k0 += 4) {
        float wa[4], wb[4], we[4];
#pragma unroll
        for (int t = 0; t < 4; ++t) {
            wa[t] = Wa1[((size_t)head*3*HD +        (k0+t))*HD + d];
            wb[t] = Wa1[((size_t)head*3*HD +   HD + (k0+t))*HD + d];
            we[t] = Wa1[((size_t)head*3*HD + 2*HD + (k0+t))*HD + d];
        }
#pragma unroll
        for (int nn = 0; nn < NT; ++nn) {
            float4 whv = *reinterpret_cast<const float4*>(&whs[nn][head*HD + k0]);
            float4 eiv = *reinterpret_cast<const float4*>(&eis[nn][head*HD + k0]);
            float4 ejv = *reinterpret_cast<const float4*>(&ejs[nn][head*HD + k0]);
            accSi[nn] = fmaf(whv.x, wa[0], accSi[nn]); accSi[nn] = fmaf(whv.y, wa[1], accSi[nn]);
            accSi[nn] = fmaf(whv.z, wa[2], accSi[nn]); accSi[nn] = fmaf(whv.w, wa[3], accSi[nn]);
            accSj[nn] = fmaf(whv.x, wb[0], accSj[nn]); accSj[nn] = fmaf(whv.y, wb[1], accSj[nn]);
            accSj[nn] = fmaf(whv.z, wb[2], accSj[nn]); accSj[nn] = fmaf(whv.w, wb[3], accSj[nn]);
            accP [nn] = fmaf(eiv.x, we[0], accP [nn]); accP [nn] = fmaf(eiv.y, we[1], accP [nn]);
            accP [nn] = fmaf(eiv.z, we[2], accP [nn]); accP [nn] = fmaf(eiv.w, we[3], accP [nn]);
            accQ [nn] = fmaf(ejv.x, we[0], accQ [nn]); accQ [nn] = fmaf(ejv.y, we[1], accQ [nn]);
            accQ [nn] = fmaf(ejv.z, we[2], accQ [nn]); accQ [nn] = fmaf(ejv.w, we[3], accQ [nn]);
        }
    }
    float bsi = ba1[head*HD + d];
#pragma unroll
    for (int nn = 0; nn < NT; ++nn) {
        size_t base = ((size_t)(b*NH + head)*NN + (n0 + nn))*HD + d;
        g_si2[base] = accSi[nn] + bsi + 0.6f*accP[nn];
        g_sj2[base] = accSj[nn]       + 0.6f*accQ[nn];
    }
}

// ---------------------------------------------------------------------------
// t2f: fused edge GEMM (bf16 mma) + softmax + hp + layernorm.
// Block = (b, head, 16 i's), 256 threads, 2 CTAs/SM.
// ---------------------------------------------------------------------------
// smem float-offset layout (total 18560 floats = 74.24 KB)
#define O_EJ    0                      // uint32[256*36] bf16x2 ej, pitch 36
#define O_WEBF  9216                   // uint32[4*8*32*2] permuted B frags
#define O_EI    11264                  // uint32[16*32] bf16x2 ei
#define O_SI    11776                  // float[16*64]
#define O_WA2   12800                  // float[64]
#define O_ET    12864                  // float[256*18]  ([j][i])
#define O_HP    17472                  // float[16*68]
#define T2_FLOATS 18560
#define T2_BYTES  (T2_FLOATS*4)

__global__ __launch_bounds__(256, 2) void t2f(
    const float* __restrict__ Wa1, const float* __restrict__ wa2,
    const int*   __restrict__ adj, const float* __restrict__ ba2,
    const float* __restrict__ ln_g, const float* __restrict__ ln_b)
{
    extern __shared__ __align__(16) float sm[];
    uint32_t* smu = reinterpret_cast<uint32_t*>(sm);

    int bx   = blockIdx.x;
    int it   = bx & 15;
    int head = (bx >> 4) & 3;
    int b    = bx >> 6;
    int i0   = it * 16;
    int tid  = threadIdx.x;
    int wid  = tid >> 5, lane = tid & 31;
    int gid  = lane >> 2, tig = lane & 3;

    size_t bh = (size_t)(b*NH + head);
    const float* sj_base = g_sj2 + bh*NN*HD;
    const float* wh_base = g_Wh  + bh*NN*HD;

    // ---- staging ----
    for (int t = tid; t < NN*32; t += 256) {           // EJ -> bf16x2
        int j = t >> 5, kk = t & 31;
        float2 v = *reinterpret_cast<const float2*>(&g_ej[(bh*NN + j)*HD + 2*kk]);
        smu[O_EJ + j*36 + kk] = packbf(v.x, v.y);
    }
    // WEBF: permuted B fragments: position lane holds frag for (tig=lane&3, gid=lane>>2)
    for (int t = tid; t < 2048; t += 256) {
        int c   = t & 1;
        int ln2 = (t >> 1) & 31;
        int q   = t >> 6;              // ks*8+nt
        int ks  = q >> 3, nt = q & 7;
        int tg  = ln2 & 3, gd = ln2 >> 2;     // FIXED mapping
        int kk  = ks*8 + tg + (c ? 4 : 0);
        int d   = nt*8 + gd;
        float f0 = 0.4f * Wa1[((size_t)head*3*HD + 2*HD + 2*kk    )*HD + d];
        float f1 = 0.4f * Wa1[((size_t)head*3*HD + 2*HD + 2*kk + 1)*HD + d];
        smu[O_WEBF + t] = packbf(f0, f1);
    }
    for (int t = tid; t < 16*32; t += 256) {           // EI -> bf16x2
        int ii = t >> 5, kk = t & 31;
        float2 v = *reinterpret_cast<const float2*>(&g_ei[(bh*NN + i0 + ii)*HD + 2*kk]);
        smu[O_EI + t] = packbf(v.x, v.y);
    }
    for (int t = tid; t < 16*64; t += 256) {           // SI fp32
        int ii = t >> 6, d = t & 63;
        sm[O_SI + t] = g_si2[(bh*NN + i0 + ii)*HD + d];
    }
    if (tid < 64) sm[O_WA2 + tid] = wa2[head*HD + tid];
    __syncthreads();

    // ---- resident B fragments (conflict-free LDS.64, loaded once) ----
    unsigned long long bfr[4][8];
#pragma unroll
    for (int ks = 0; ks < 4; ++ks)
#pragma unroll
        for (int nt = 0; nt < 8; ++nt)
            bfr[ks][nt] = *reinterpret_cast<const unsigned long long*>(
                &smu[O_WEBF + ((ks*8 + nt)*32 + lane)*2]);

    // ---- edge phase ----
    for (int ii = 0; ii < 16; ++ii) {
        uint32_t eir[8];
#pragma unroll
        for (int ks = 0; ks < 4; ++ks) {
            eir[2*ks]   = smu[O_EI + ii*32 + ks*8 + tig];
            eir[2*ks+1] = smu[O_EI + ii*32 + ks*8 + 4 + tig];
        }
#pragma unroll
        for (int p = 0; p < 2; ++p) {
            int j0 = (wid + 8*p) * 16;
            int r0 = j0 + gid, r1 = r0 + 8;

            float acc[8][4];
#pragma unroll
            for (int nt = 0; nt < 8; ++nt) {
                float2 s = *reinterpret_cast<const float2*>(&sm[O_SI + ii*64 + nt*8 + 2*tig]);
                acc[nt][0] = s.x; acc[nt][1] = s.y; acc[nt][2] = s.x; acc[nt][3] = s.y;
            }
#pragma unroll
            for (int ks = 0; ks < 4; ++ks) {
                uint32_t a0 = habs2(hadd2(smu[O_EJ + r0*36 + ks*8 + tig],     eir[2*ks]));
                uint32_t a1 = habs2(hadd2(smu[O_EJ + r1*36 + ks*8 + tig],     eir[2*ks]));
                uint32_t a2 = habs2(hadd2(smu[O_EJ + r0*36 + ks*8 + 4 + tig], eir[2*ks+1]));
                uint32_t a3 = habs2(hadd2(smu[O_EJ + r1*36 + ks*8 + 4 + tig], eir[2*ks+1]));
#pragma unroll
                for (int nt = 0; nt < 8; ++nt) {
                    uint32_t b0 = (uint32_t)(bfr[ks][nt] & 0xffffffffu);
                    uint32_t b1 = (uint32_t)(bfr[ks][nt] >> 32);
                    mma16816(acc[nt], a0, a1, a2, a3, b0, b1);
                }
            }
            // epilogue
            float pe0 = 0.f, pe1 = 0.f;
#pragma unroll
            for (int nt = 0; nt < 8; ++nt) {
                int d = nt*8 + 2*tig;
                float2 sj0 = *reinterpret_cast<const float2*>(&sj_base[(size_t)r0*HD + d]);
                float2 sj1 = *reinterpret_cast<const float2*>(&sj_base[(size_t)r1*HD + d]);
                float2 w2  = *reinterpret_cast<const float2*>(&sm[O_WA2 + d]);
                float v00 = acc[nt][0] + sj0.x, v01 = acc[nt][1] + sj0.y;
                float v10 = acc[nt][2] + sj1.x, v11 = acc[nt][3] + sj1.y;
                pe0 = fmaf(fmaxf(v00, ALPHA*v00), w2.x, pe0);
                pe0 = fmaf(fmaxf(v01, ALPHA*v01), w2.y, pe0);
                pe1 = fmaf(fmaxf(v10, ALPHA*v10), w2.x, pe1);
                pe1 = fmaf(fmaxf(v11, ALPHA*v11), w2.y, pe1);
            }
            pe0 += __shfl_xor_sync(0xffffffffu, pe0, 1);
            pe0 += __shfl_xor_sync(0xffffffffu, pe0, 2);
            pe1 += __shfl_xor_sync(0xffffffffu, pe1, 1);
            pe1 += __shfl_xor_sync(0xffffffffu, pe1, 2);
            if (tig == 0) {
                sm[O_ET + r0*18 + ii] = pe0;
                sm[O_ET + r1*18 + ii] = pe1;
            }
        }
    }
    __syncthreads();

    // ---- masked softmax: warp handles i = 2*wid + r ----
    {
        float bav = ba2[head];
#pragma unroll
        for (int r = 0; r < 2; ++r) {
            int i = wid*2 + r;
            int iglob = i0 + i;
            float vals[8]; float mx = -1e30f;
#pragma unroll
            for (int s = 0; s < 8; ++s) {
                int j = lane + 32*s;
                float pe = sm[O_ET + j*18 + i] + bav;
                int a = adj[((size_t)b*NN + iglob)*NN + j];
                vals[s] = (a == 0) ? -1e9f : pe;
                mx = fmaxf(mx, vals[s]);
            }
#pragma unroll
            for (int o = 16; o; o >>= 1) mx = fmaxf(mx, __shfl_xor_sync(0xffffffffu, mx, o));
            float se = 0.f;
#pragma unroll
            for (int s = 0; s < 8; ++s) { vals[s] = __expf(vals[s] - mx); se += vals[s]; }
#pragma unroll
            for (int o = 16; o; o >>= 1) se += __shfl_xor_sync(0xffffffffu, se, o);
            float inv = 1.0f / se;
#pragma unroll
            for (int s = 0; s < 8; ++s)
                sm[O_ET + (lane + 32*s)*18 + i] = vals[s] * inv;
        }
    }
    __syncthreads();

    // ---- hp[i][d] = sum_j attn[i][j] * Wh[j][d] ----
    {
        int d = tid & 63, ig = tid >> 6;    // ig 0..3 -> pairs ig and ig+4
        unsigned long long accA = 0ull, accB = 0ull;
#pragma unroll 4
        for (int j = 0; j < NN; ++j) {
            unsigned long long wh2 = pack2(wh_base[(size_t)j*HD + d]);
            unsigned long long atA = *reinterpret_cast<const unsigned long long*>(&sm[O_ET + j*18 + 2*ig]);
            unsigned long long atB = *reinterpret_cast<const unsigned long long*>(&sm[O_ET + j*18 + 2*(ig+4)]);
            fma2(accA, atA, wh2);
            fma2(accB, atB, wh2);
        }
        float a0, a1, b0v, b1v;
        unpack2(accA, a0, a1);
        unpack2(accB, b0v, b1v);
        sm[O_HP + (2*ig    )*68 + d] = a0;
        sm[O_HP + (2*ig + 1)*68 + d] = a1;
        sm[O_HP + (2*(ig+4)    )*68 + d] = b0v;
        sm[O_HP + (2*(ig+4) + 1)*68 + d] = b1v;
    }
    __syncthreads();

    // ---- per-head layernorm: warp handles i = 2*wid + r ----
    {
#pragma unroll
        for (int r = 0; r < 2; ++r) {
            int i = wid*2 + r;
            float x0 = sm[O_HP + i*68 + lane];
            float x1 = sm[O_HP + i*68 + 32 + lane];
            float s1 = x0 + x1, s2 = x0*x0 + x1*x1;
#pragma unroll
            for (int o = 16; o; o >>= 1) {
                s1 += __shfl_xor_sync(0xffffffffu, s1, o);
                s2 += __shfl_xor_sync(0xffffffffu, s2, o);
            }
            float m   = s1 * (1.0f/64.0f);
            float var = s2 * (1.0f/64.0f) - m*m;
            float rr  = rsqrtf(var + 1e-5f);
            size_t obase = ((size_t)(b*NN) + i0 + i)*FIN + head*HD;
            g_concat[obase + lane]      = (x0 - m)*rr*ln_g[head*HD + lane]      + ln_b[head*HD + lane];
            g_concat[obase + 32 + lane] = (x1 - m)*rr*ln_g[head*HD + 32 + lane] + ln_b[head*HD + 32 + lane];
        }
    }
}

// ---------------------------------------------------------------------------
// Kernel 3: NT=4, high occupancy, scalar FFMA.
// ---------------------------------------------------------------------------
__global__ __launch_bounds__(256) void k3_out(
    const float* __restrict__ hin, const float* __restrict__ Wo,
    const float* __restrict__ bo,  const float* __restrict__ g2,
    const float* __restrict__ b2,  float* __restrict__ out)
{
    const int NT = 4;
    int b  = blockIdx.x >> 6;
    int n0 = (blockIdx.x & 63) * NT;
    int tid = threadIdx.x;

    __shared__ float cs [NT][FIN];
    __shared__ float hs2[NT][FIN];
    __shared__ float red[NT][2][2];

    for (int nn = 0; nn < NT; ++nn) {
        cs [nn][tid] = g_concat[((size_t)b*NN + n0 + nn)*FIN + tid];
        hs2[nn][tid] = hin     [((size_t)b*NN + n0 + nn)*FIN + tid];
    }
    __syncthreads();

    float bv = bo[tid];
    float acc[NT];
#pragma unroll
    for (int nn = 0; nn < NT; ++nn) acc[nn] = bv;

#pragma unroll 4
    for (int f = 0; f < FIN; ++f) {
        float w = Wo[(size_t)f*FIN + tid];
#pragma unroll
        for (int nn = 0; nn < NT; ++nn)
            acc[nn] = fmaf(cs[nn][f], w, acc[nn]);
    }
    __syncthreads();
    for (int nn = 0; nn < NT; ++nn)
        cs[nn][tid] = acc[nn] + hs2[nn][tid];
    __syncthreads();

    // layernorm: two warps per row
    int wid = tid >> 5, lane = tid & 31;
    int row = wid >> 1, half = wid & 1;
    float s1 = 0.f, s2 = 0.f;
#pragma unroll
    for (int k = 0; k < 4; ++k) {
        float x = cs[row][half*128 + k*32 + lane];
        s1 += x; s2 += x*x;
    }
#pragma unroll
    for (int o = 16; o; o >>= 1) {
        s1 += __shfl_xor_sync(0xffffffffu, s1, o);
        s2 += __shfl_xor_sync(0xffffffffu, s2, o);
    }
    if (lane == 0) { red[row][half][0] = s1; red[row][half][1] = s2; }
    __syncthreads();

    {
        int r2 = tid >> 6, o = tid & 63;
        float t1 = red[r2][0][0] + red[r2][1][0];
        float t2 = red[r2][0][1] + red[r2][1][1];
        float m   = t1 * (1.0f/256.0f);
        float var = t2 * (1.0f/256.0f) - m*m;
        float rr  = rsqrtf(var + 1e-5f);
#pragma unroll
        for (int k = 0; k < 4; ++k) {
            int c = o + k*64;
            float x = cs[r2][c];
            out[((size_t)b*NN + n0 + r2)*FIN + c] = (x - m)*rr*g2[c] + b2[c];
        }
    }
}

// ---------------------------------------------------------------------------
extern "C" void kernel_launch(void* const* d_in, const int* in_sizes, int n_in,
                              void* d_out, int out_size)
{
    const float* h    = (const float*)d_in[0];
    const int*   adj  = (const int*)  d_in[1];
    const float* W    = (const float*)d_in[2];
    const float* We1  = (const float*)d_in[3];
    const float* be1  = (const float*)d_in[4];
    const float* Wa1  = (const float*)d_in[5];
    const float* ba1  = (const float*)d_in[6];
    const float* wa2  = (const float*)d_in[7];
    const float* ba2  = (const float*)d_in[8];
    const float* ln_g = (const float*)d_in[9];
    const float* ln_b = (const float*)d_in[10];
    const float* Wo   = (const float*)d_in[11];
    const float* bo   = (const float*)d_in[12];
    const float* g2   = (const float*)d_in[13];
    const float* b2   = (const float*)d_in[14];
    float* out = (float*)d_out;

    cudaFuncSetAttribute(t2f, cudaFuncAttributeMaxDynamicSharedMemorySize, T2_BYTES);

    k1_proj<<<NB*(NN/4), 256>>>(h, W, We1, be1, Wa1, ba1);
    t2f    <<<NB*NH*(NN/16), 256, T2_BYTES>>>(Wa1, wa2, adj, ba2, ln_g, ln_b);
    k3_out <<<NB*(NN/4), 256>>>(h, Wo, bo, g2, b2, out);
}

// round 8
// speedup vs baseline: 1.0438x; 1.0438x over previous
#include <cuda_runtime.h>
#include <math.h>
#include <stdint.h>

#define NB   8
#define NN   256
#define NH   4
#define HD   64
#define FIN  256
#define ALPHA 0.2f

// ---------------- scratch (__device__ globals; no allocs allowed) ----------
__device__ float g_Wh [NB*NH*NN*HD];
__device__ float g_si2[NB*NH*NN*HD];   // si + ba1 + 0.6*(ei@We)
__device__ float g_sj2[NB*NH*NN*HD];   // sj + 0.6*(ej@We)
__device__ float g_ei [NB*NH*NN*HD];
__device__ float g_ej [NB*NH*NN*HD];
__device__ float g_concat[NB*NN*FIN];

// ---------------- packed helpers -------------------------------------------
__device__ __forceinline__ unsigned long long pack2(float v) {
    unsigned long long r; unsigned u = __float_as_uint(v);
    asm("mov.b64 %0, {%1, %1};" : "=l"(r) : "r"(u));
    return r;
}
__device__ __forceinline__ void fma2(unsigned long long& d,
                                     unsigned long long a, unsigned long long b) {
    asm("fma.rn.f32x2 %0, %1, %2, %0;" : "+l"(d) : "l"(a), "l"(b));
}
__device__ __forceinline__ void unpack2(unsigned long long v, float& lo, float& hi) {
    unsigned a, b;
    asm("mov.b64 {%0, %1}, %2;" : "=r"(a), "=r"(b) : "l"(v));
    lo = __uint_as_float(a); hi = __uint_as_float(b);
}
__device__ __forceinline__ uint32_t packbf(float lo, float hi) {   // low half = lo
    uint32_t r;
    asm("cvt.rn.bf16x2.f32 %0, %1, %2;" : "=r"(r) : "f"(hi), "f"(lo));
    return r;
}
__device__ __forceinline__ uint32_t hadd2(uint32_t a, uint32_t b) {
    uint32_t r;
    asm("add.rn.bf16x2 %0, %1, %2;" : "=r"(r) : "r"(a), "r"(b));
    return r;
}
__device__ __forceinline__ uint32_t habs2(uint32_t a) { return a & 0x7FFF7FFFu; }

__device__ __forceinline__ void mma16816(float* c, uint32_t a0, uint32_t a1,
                                         uint32_t a2, uint32_t a3,
                                         uint32_t b0, uint32_t b1) {
    asm volatile("mma.sync.aligned.m16n8k16.row.col.f32.bf16.bf16.f32 "
                 "{%0,%1,%2,%3}, {%4,%5,%6,%7}, {%8,%9}, {%0,%1,%2,%3};"
                 : "+f"(c[0]), "+f"(c[1]), "+f"(c[2]), "+f"(c[3])
                 : "r"(a0), "r"(a1), "r"(a2), "r"(a3), "r"(b0), "r"(b1));
}

// ---------------------------------------------------------------------------
// Kernel 1: NT=16, transposed smem staging for high FFMA density.
// Phase A: Wh/ei/ej = h @ {W, We1a, We1b}.  Phase B: si2/sj2 via per-head
// transposed tiles (broadcast float4 reads).
// ---------------------------------------------------------------------------
// dynamic smem float offsets (pitch 20 words = 80B, float4-aligned)
#define K1_HST  0                      // [256 f][20]   (h transposed, 16 rows)
#define K1_WHT  5120                   // [4 head][64 k][20]
#define K1_EIT  10240
#define K1_EJT  15360
#define K1_FLOATS 20480
#define K1_BYTES  (K1_FLOATS*4)        // 81920

__global__ __launch_bounds__(256) void k1_proj(
    const float* __restrict__ hin, const float* __restrict__ W,
    const float* __restrict__ We1, const float* __restrict__ be1,
    const float* __restrict__ Wa1, const float* __restrict__ ba1)
{
    extern __shared__ __align__(16) float s1[];
    const int NT = 16;
    int b  = blockIdx.x >> 4;
    int n0 = (blockIdx.x & 15) * NT;
    int tid = threadIdx.x;
    int head = tid >> 6, d = tid & 63;

    // stage h transposed: hst[f][nn]
#pragma unroll
    for (int nn = 0; nn < NT; ++nn)
        s1[K1_HST + tid*20 + nn] = hin[((size_t)(b*NN + n0 + nn))*FIN + tid];
    __syncthreads();

    float accW[NT], accE1[NT], accE2[NT];
#pragma unroll
    for (int nn = 0; nn < NT; ++nn) { accW[nn]=0.f; accE1[nn]=0.f; accE2[nn]=0.f; }

#pragma unroll 4
    for (int f = 0; f < FIN; ++f) {
        float wv = W  [((size_t)head*FIN + f)*HD + d];
        float w1 = We1[((size_t)head*2*FIN + f)*HD + d];
        float w2 = We1[((size_t)head*2*FIN + FIN + f)*HD + d];
#pragma unroll
        for (int p = 0; p < 4; ++p) {
            float4 h4 = *reinterpret_cast<const float4*>(&s1[K1_HST + f*20 + 4*p]);
            accW [4*p+0] = fmaf(h4.x, wv, accW [4*p+0]);
            accW [4*p+1] = fmaf(h4.y, wv, accW [4*p+1]);
            accW [4*p+2] = fmaf(h4.z, wv, accW [4*p+2]);
            accW [4*p+3] = fmaf(h4.w, wv, accW [4*p+3]);
            accE1[4*p+0] = fmaf(h4.x, w1, accE1[4*p+0]);
            accE1[4*p+1] = fmaf(h4.y, w1, accE1[4*p+1]);
            accE1[4*p+2] = fmaf(h4.z, w1, accE1[4*p+2]);
            accE1[4*p+3] = fmaf(h4.w, w1, accE1[4*p+3]);
            accE2[4*p+0] = fmaf(h4.x, w2, accE2[4*p+0]);
            accE2[4*p+1] = fmaf(h4.y, w2, accE2[4*p+1]);
            accE2[4*p+2] = fmaf(h4.z, w2, accE2[4*p+2]);
            accE2[4*p+3] = fmaf(h4.w, w2, accE2[4*p+3]);
        }
    }

    float bei = be1[head*HD + d];
    int kidx = (head*HD + d)*20;
#pragma unroll
    for (int nn = 0; nn < NT; ++nn) {
        size_t base = ((size_t)(b*NH + head)*NN + (n0 + nn))*HD + d;
        float e1 = accE1[nn] + bei;
        g_Wh[base] = accW[nn];
        g_ei[base] = e1;
        g_ej[base] = accE2[nn];
        s1[K1_WHT + kidx + nn] = accW[nn];
        s1[K1_EIT + kidx + nn] = e1;
        s1[K1_EJT + kidx + nn] = accE2[nn];
    }
    __syncthreads();

    float accSi[NT], accSj[NT], accP[NT], accQ[NT];
#pragma unroll
    for (int nn = 0; nn < NT; ++nn) { accSi[nn]=0.f; accSj[nn]=0.f; accP[nn]=0.f; accQ[nn]=0.f; }

#pragma unroll 2
    for (int k = 0; k < HD; ++k) {
        float wa = Wa1[((size_t)head*3*HD +        k)*HD + d];
        float wb = Wa1[((size_t)head*3*HD +   HD + k)*HD + d];
        float we = Wa1[((size_t)head*3*HD + 2*HD + k)*HD + d];
        int kb = (head*HD + k)*20;
#pragma unroll
        for (int p = 0; p < 4; ++p) {
            float4 wh4 = *reinterpret_cast<const float4*>(&s1[K1_WHT + kb + 4*p]);
            float4 ei4 = *reinterpret_cast<const float4*>(&s1[K1_EIT + kb + 4*p]);
            float4 ej4 = *reinterpret_cast<const float4*>(&s1[K1_EJT + kb + 4*p]);
            accSi[4*p+0] = fmaf(wh4.x, wa, accSi[4*p+0]);
            accSi[4*p+1] = fmaf(wh4.y, wa, accSi[4*p+1]);
            accSi[4*p+2] = fmaf(wh4.z, wa, accSi[4*p+2]);
            accSi[4*p+3] = fmaf(wh4.w, wa, accSi[4*p+3]);
            accSj[4*p+0] = fmaf(wh4.x, wb, accSj[4*p+0]);
            accSj[4*p+1] = fmaf(wh4.y, wb, accSj[4*p+1]);
            accSj[4*p+2] = fmaf(wh4.z, wb, accSj[4*p+2]);
            accSj[4*p+3] = fmaf(wh4.w, wb, accSj[4*p+3]);
            accP [4*p+0] = fmaf(ei4.x, we, accP [4*p+0]);
            accP [4*p+1] = fmaf(ei4.y, we, accP [4*p+1]);
            accP [4*p+2] = fmaf(ei4.z, we, accP [4*p+2]);
            accP [4*p+3] = fmaf(ei4.w, we, accP [4*p+3]);
            accQ [4*p+0] = fmaf(ej4.x, we, accQ [4*p+0]);
            accQ [4*p+1] = fmaf(ej4.y, we, accQ [4*p+1]);
            accQ [4*p+2] = fmaf(ej4.z, we, accQ [4*p+2]);
            accQ [4*p+3] = fmaf(ej4.w, we, accQ [4*p+3]);
        }
    }
    float bsi = ba1[head*HD + d];
#pragma unroll
    for (int nn = 0; nn < NT; ++nn) {
        size_t base = ((size_t)(b*NH + head)*NN + (n0 + nn))*HD + d;
        g_si2[base] = accSi[nn] + bsi + 0.6f*accP[nn];
        g_sj2[base] = accSj[nn]       + 0.6f*accQ[nn];
    }
}

// ---------------------------------------------------------------------------
// t2f: fused edge GEMM (bf16 mma) + softmax + hp + layernorm.
// (unchanged from R7 — passing at rel_err 9.2e-5)
// ---------------------------------------------------------------------------
#define O_EJ    0                      // uint32[256*36] bf16x2 ej, pitch 36
#define O_WEBF  9216                   // uint32[4*8*32*2] permuted B frags
#define O_EI    11264                  // uint32[16*32] bf16x2 ei
#define O_SI    11776                  // float[16*64]
#define O_WA2   12800                  // float[64]
#define O_ET    12864                  // float[256*18]  ([j][i])
#define O_HP    17472                  // float[16*68]
#define T2_FLOATS 18560
#define T2_BYTES  (T2_FLOATS*4)

__global__ __launch_bounds__(256, 2) void t2f(
    const float* __restrict__ Wa1, const float* __restrict__ wa2,
    const int*   __restrict__ adj, const float* __restrict__ ba2,
    const float* __restrict__ ln_g, const float* __restrict__ ln_b)
{
    extern __shared__ __align__(16) float sm[];
    uint32_t* smu = reinterpret_cast<uint32_t*>(sm);

    int bx   = blockIdx.x;
    int it   = bx & 15;
    int head = (bx >> 4) & 3;
    int b    = bx >> 6;
    int i0   = it * 16;
    int tid  = threadIdx.x;
    int wid  = tid >> 5, lane = tid & 31;
    int gid  = lane >> 2, tig = lane & 3;

    size_t bh = (size_t)(b*NH + head);
    const float* sj_base = g_sj2 + bh*NN*HD;
    const float* wh_base = g_Wh  + bh*NN*HD;

    for (int t = tid; t < NN*32; t += 256) {
        int j = t >> 5, kk = t & 31;
        float2 v = *reinterpret_cast<const float2*>(&g_ej[(bh*NN + j)*HD + 2*kk]);
        smu[O_EJ + j*36 + kk] = packbf(v.x, v.y);
    }
    for (int t = tid; t < 2048; t += 256) {
        int c   = t & 1;
        int ln2 = (t >> 1) & 31;
        int q   = t >> 6;
        int ks  = q >> 3, nt = q & 7;
        int tg  = ln2 & 3, gd = ln2 >> 2;
        int kk  = ks*8 + tg + (c ? 4 : 0);
        int d   = nt*8 + gd;
        float f0 = 0.4f * Wa1[((size_t)head*3*HD + 2*HD + 2*kk    )*HD + d];
        float f1 = 0.4f * Wa1[((size_t)head*3*HD + 2*HD + 2*kk + 1)*HD + d];
        smu[O_WEBF + t] = packbf(f0, f1);
    }
    for (int t = tid; t < 16*32; t += 256) {
        int ii = t >> 5, kk = t & 31;
        float2 v = *reinterpret_cast<const float2*>(&g_ei[(bh*NN + i0 + ii)*HD + 2*kk]);
        smu[O_EI + t] = packbf(v.x, v.y);
    }
    for (int t = tid; t < 16*64; t += 256) {
        int ii = t >> 6, d = t & 63;
        sm[O_SI + t] = g_si2[(bh*NN + i0 + ii)*HD + d];
    }
    if (tid < 64) sm[O_WA2 + tid] = wa2[head*HD + tid];
    __syncthreads();

    unsigned long long bfr[4][8];
#pragma unroll
    for (int ks = 0; ks < 4; ++ks)
#pragma unroll
        for (int nt = 0; nt < 8; ++nt)
            bfr[ks][nt] = *reinterpret_cast<const unsigned long long*>(
                &smu[O_WEBF + ((ks*8 + nt)*32 + lane)*2]);

    for (int ii = 0; ii < 16; ++ii) {
        uint32_t eir[8];
#pragma unroll
        for (int ks = 0; ks < 4; ++ks) {
            eir[2*ks]   = smu[O_EI + ii*32 + ks*8 + tig];
            eir[2*ks+1] = smu[O_EI + ii*32 + ks*8 + 4 + tig];
        }
#pragma unroll
        for (int p = 0; p < 2; ++p) {
            int j0 = (wid + 8*p) * 16;
            int r0 = j0 + gid, r1 = r0 + 8;

            float acc[8][4];
#pragma unroll
            for (int nt = 0; nt < 8; ++nt) {
                float2 s = *reinterpret_cast<const float2*>(&sm[O_SI + ii*64 + nt*8 + 2*tig]);
                acc[nt][0] = s.x; acc[nt][1] = s.y; acc[nt][2] = s.x; acc[nt][3] = s.y;
            }
#pragma unroll
            for (int ks = 0; ks < 4; ++ks) {
                uint32_t a0 = habs2(hadd2(smu[O_EJ + r0*36 + ks*8 + tig],     eir[2*ks]));
                uint32_t a1 = habs2(hadd2(smu[O_EJ + r1*36 + ks*8 + tig],     eir[2*ks]));
                uint32_t a2 = habs2(hadd2(smu[O_EJ + r0*36 + ks*8 + 4 + tig], eir[2*ks+1]));
                uint32_t a3 = habs2(hadd2(smu[O_EJ + r1*36 + ks*8 + 4 + tig], eir[2*ks+1]));
#pragma unroll
                for (int nt = 0; nt < 8; ++nt) {
                    uint32_t b0 = (uint32_t)(bfr[ks][nt] & 0xffffffffu);
                    uint32_t b1 = (uint32_t)(bfr[ks][nt] >> 32);
                    mma16816(acc[nt], a0, a1, a2, a3, b0, b1);
                }
            }
            float pe0 = 0.f, pe1 = 0.f;
#pragma unroll
            for (int nt = 0; nt < 8; ++nt) {
                int d = nt*8 + 2*tig;
                float2 sj0 = *reinterpret_cast<const float2*>(&sj_base[(size_t)r0*HD + d]);
                float2 sj1 = *reinterpret_cast<const float2*>(&sj_base[(size_t)r1*HD + d]);
                float2 w2  = *reinterpret_cast<const float2*>(&sm[O_WA2 + d]);
                float v00 = acc[nt][0] + sj0.x, v01 = acc[nt][1] + sj0.y;
                float v10 = acc[nt][2] + sj1.x, v11 = acc[nt][3] + sj1.y;
                pe0 = fmaf(fmaxf(v00, ALPHA*v00), w2.x, pe0);
                pe0 = fmaf(fmaxf(v01, ALPHA*v01), w2.y, pe0);
                pe1 = fmaf(fmaxf(v10, ALPHA*v10), w2.x, pe1);
                pe1 = fmaf(fmaxf(v11, ALPHA*v11), w2.y, pe1);
            }
            pe0 += __shfl_xor_sync(0xffffffffu, pe0, 1);
            pe0 += __shfl_xor_sync(0xffffffffu, pe0, 2);
            pe1 += __shfl_xor_sync(0xffffffffu, pe1, 1);
            pe1 += __shfl_xor_sync(0xffffffffu, pe1, 2);
            if (tig == 0) {
                sm[O_ET + r0*18 + ii] = pe0;
                sm[O_ET + r1*18 + ii] = pe1;
            }
        }
    }
    __syncthreads();

    {
        float bav = ba2[head];
#pragma unroll
        for (int r = 0; r < 2; ++r) {
            int i = wid*2 + r;
            int iglob = i0 + i;
            float vals[8]; float mx = -1e30f;
#pragma unroll
            for (int s = 0; s < 8; ++s) {
                int j = lane + 32*s;
                float pe = sm[O_ET + j*18 + i] + bav;
                int a = adj[((size_t)b*NN + iglob)*NN + j];
                vals[s] = (a == 0) ? -1e9f : pe;
                mx = fmaxf(mx, vals[s]);
            }
#pragma unroll
            for (int o = 16; o; o >>= 1) mx = fmaxf(mx, __shfl_xor_sync(0xffffffffu, mx, o));
            float se = 0.f;
#pragma unroll
            for (int s = 0; s < 8; ++s) { vals[s] = __expf(vals[s] - mx); se += vals[s]; }
#pragma unroll
            for (int o = 16; o; o >>= 1) se += __shfl_xor_sync(0xffffffffu, se, o);
            float inv = 1.0f / se;
#pragma unroll
            for (int s = 0; s < 8; ++s)
                sm[O_ET + (lane + 32*s)*18 + i] = vals[s] * inv;
        }
    }
    __syncthreads();

    {
        int d = tid & 63, ig = tid >> 6;
        unsigned long long accA = 0ull, accB = 0ull;
#pragma unroll 4
        for (int j = 0; j < NN; ++j) {
            unsigned long long wh2 = pack2(wh_base[(size_t)j*HD + d]);
            unsigned long long atA = *reinterpret_cast<const unsigned long long*>(&sm[O_ET + j*18 + 2*ig]);
            unsigned long long atB = *reinterpret_cast<const unsigned long long*>(&sm[O_ET + j*18 + 2*(ig+4)]);
            fma2(accA, atA, wh2);
            fma2(accB, atB, wh2);
        }
        float a0, a1, b0v, b1v;
        unpack2(accA, a0, a1);
        unpack2(accB, b0v, b1v);
        sm[O_HP + (2*ig    )*68 + d] = a0;
        sm[O_HP + (2*ig + 1)*68 + d] = a1;
        sm[O_HP + (2*(ig+4)    )*68 + d] = b0v;
        sm[O_HP + (2*(ig+4) + 1)*68 + d] = b1v;
    }
    __syncthreads();

    {
#pragma unroll
        for (int r = 0; r < 2; ++r) {
            int i = wid*2 + r;
            float x0 = sm[O_HP + i*68 + lane];
            float x1 = sm[O_HP + i*68 + 32 + lane];
            float s1 = x0 + x1, s2 = x0*x0 + x1*x1;
#pragma unroll
            for (int o = 16; o; o >>= 1) {
                s1 += __shfl_xor_sync(0xffffffffu, s1, o);
                s2 += __shfl_xor_sync(0xffffffffu, s2, o);
            }
            float m   = s1 * (1.0f/64.0f);
            float var = s2 * (1.0f/64.0f) - m*m;
            float rr  = rsqrtf(var + 1e-5f);
            size_t obase = ((size_t)(b*NN) + i0 + i)*FIN + head*HD;
            g_concat[obase + lane]      = (x0 - m)*rr*ln_g[head*HD + lane]      + ln_b[head*HD + lane];
            g_concat[obase + 32 + lane] = (x1 - m)*rr*ln_g[head*HD + 32 + lane] + ln_b[head*HD + 32 + lane];
        }
    }
}

// ---------------------------------------------------------------------------
// Kernel 3: NT=16, transposed staging, scalar FFMA, fused residual+layernorm.
// ---------------------------------------------------------------------------
__global__ __launch_bounds__(256) void k3_out(
    const float* __restrict__ hin, const float* __restrict__ Wo,
    const float* __restrict__ bo,  const float* __restrict__ g2,
    const float* __restrict__ b2,  float* __restrict__ out)
{
    const int NT = 16;
    int b  = blockIdx.x >> 4;
    int n0 = (blockIdx.x & 15) * NT;
    int tid = threadIdx.x;

    __shared__ __align__(16) float cst[FIN*20];   // transposed concat
    __shared__ float hs2[NT][FIN];

#pragma unroll
    for (int nn = 0; nn < NT; ++nn) {
        cst[tid*20 + nn] = g_concat[((size_t)b*NN + n0 + nn)*FIN + tid];
        hs2[nn][tid]     = hin     [((size_t)b*NN + n0 + nn)*FIN + tid];
    }
    __syncthreads();

    float bv = bo[tid];
    float acc[NT];
#pragma unroll
    for (int nn = 0; nn < NT; ++nn) acc[nn] = bv;

#pragma unroll 4
    for (int f = 0; f < FIN; ++f) {
        float w = Wo[(size_t)f*FIN + tid];
#pragma unroll
        for (int p = 0; p < 4; ++p) {
            float4 c4 = *reinterpret_cast<const float4*>(&cst[f*20 + 4*p]);
            acc[4*p+0] = fmaf(c4.x, w, acc[4*p+0]);
            acc[4*p+1] = fmaf(c4.y, w, acc[4*p+1]);
            acc[4*p+2] = fmaf(c4.z, w, acc[4*p+2]);
            acc[4*p+3] = fmaf(c4.w, w, acc[4*p+3]);
        }
    }
    __syncthreads();
#pragma unroll
    for (int nn = 0; nn < NT; ++nn)
        hs2[nn][tid] = acc[nn] + hs2[nn][tid];
    __syncthreads();

    // layernorm: warp handles rows 2*wid, 2*wid+1
    int wid = tid >> 5, lane = tid & 31;
#pragma unroll
    for (int r = 0; r < 2; ++r) {
        int row = wid*2 + r;
        float s1 = 0.f, s2 = 0.f;
#pragma unroll
        for (int k = 0; k < 8; ++k) {
            float x = hs2[row][k*32 + lane];
            s1 += x; s2 += x*x;
        }
#pragma unroll
        for (int o = 16; o; o >>= 1) {
            s1 += __shfl_xor_sync(0xffffffffu, s1, o);
            s2 += __shfl_xor_sync(0xffffffffu, s2, o);
        }
        float m   = s1 * (1.0f/256.0f);
        float var = s2 * (1.0f/256.0f) - m*m;
        float rr  = rsqrtf(var + 1e-5f);
#pragma unroll
        for (int k = 0; k < 8; ++k) {
            int c = k*32 + lane;
            float x = hs2[row][c];
            out[((size_t)b*NN + n0 + row)*FIN + c] = (x - m)*rr*g2[c] + b2[c];
        }
    }
}

// ---------------------------------------------------------------------------
extern "C" void kernel_launch(void* const* d_in, const int* in_sizes, int n_in,
                              void* d_out, int out_size)
{
    const float* h    = (const float*)d_in[0];
    const int*   adj  = (const int*)  d_in[1];
    const float* W    = (const float*)d_in[2];
    const float* We1  = (const float*)d_in[3];
    const float* be1  = (const float*)d_in[4];
    const float* Wa1  = (const float*)d_in[5];
    const float* ba1  = (const float*)d_in[6];
    const float* wa2  = (const float*)d_in[7];
    const float* ba2  = (const float*)d_in[8];
    const float* ln_g = (const float*)d_in[9];
    const float* ln_b = (const float*)d_in[10];
    const float* Wo   = (const float*)d_in[11];
    const float* bo   = (const float*)d_in[12];
    const float* g2   = (const float*)d_in[13];
    const float* b2   = (const float*)d_in[14];
    float* out = (float*)d_out;

    cudaFuncSetAttribute(k1_proj, cudaFuncAttributeMaxDynamicSharedMemorySize, K1_BYTES);
    cudaFuncSetAttribute(t2f,     cudaFuncAttributeMaxDynamicSharedMemorySize, T2_BYTES);

    k1_proj<<<NB*(NN/16), 256, K1_BYTES>>>(h, W, We1, be1, Wa1, ba1);
    t2f    <<<NB*NH*(NN/16), 256, T2_BYTES>>>(Wa1, wa2, adj, ba2, ln_g, ln_b);
    k3_out <<<NB*(NN/16), 256>>>(h, Wo, bo, g2, b2, out);
}

// round 9
// speedup vs baseline: 1.0619x; 1.0174x over previous
#include <cuda_runtime.h>
#include <math.h>
#include <stdint.h>

#define NB   8
#define NN   256
#define NH   4
#define HD   64
#define FIN  256
#define ALPHA 0.2f

// ---------------- scratch (__device__ globals; no allocs allowed) ----------
__device__ float g_Wh [NB*NH*NN*HD];
__device__ float g_si2[NB*NH*NN*HD];   // si + ba1 + 0.6*(ei@We)
__device__ float g_sj2[NB*NH*NN*HD];   // sj + 0.6*(ej@We)
__device__ float g_ei [NB*NH*NN*HD];
__device__ float g_ej [NB*NH*NN*HD];
__device__ float g_concat[NB*NN*FIN];

// ---------------- packed helpers -------------------------------------------
__device__ __forceinline__ unsigned long long pack2(float v) {
    unsigned long long r; unsigned u = __float_as_uint(v);
    asm("mov.b64 %0, {%1, %1};" : "=l"(r) : "r"(u));
    return r;
}
__device__ __forceinline__ void fma2(unsigned long long& d,
                                     unsigned long long a, unsigned long long b) {
    asm("fma.rn.f32x2 %0, %1, %2, %0;" : "+l"(d) : "l"(a), "l"(b));
}
__device__ __forceinline__ void unpack2(unsigned long long v, float& lo, float& hi) {
    unsigned a, b;
    asm("mov.b64 {%0, %1}, %2;" : "=r"(a), "=r"(b) : "l"(v));
    lo = __uint_as_float(a); hi = __uint_as_float(b);
}
__device__ __forceinline__ uint32_t packbf(float lo, float hi) {   // low half = lo
    uint32_t r;
    asm("cvt.rn.bf16x2.f32 %0, %1, %2;" : "=r"(r) : "f"(hi), "f"(lo));
    return r;
}
__device__ __forceinline__ uint32_t hadd2(uint32_t a, uint32_t b) {
    uint32_t r;
    asm("add.rn.bf16x2 %0, %1, %2;" : "=r"(r) : "r"(a), "r"(b));
    return r;
}
__device__ __forceinline__ uint32_t habs2(uint32_t a) { return a & 0x7FFF7FFFu; }

__device__ __forceinline__ void mma16816(float* c, uint32_t a0, uint32_t a1,
                                         uint32_t a2, uint32_t a3,
                                         uint32_t b0, uint32_t b1) {
    asm volatile("mma.sync.aligned.m16n8k16.row.col.f32.bf16.bf16.f32 "
                 "{%0,%1,%2,%3}, {%4,%5,%6,%7}, {%8,%9}, {%0,%1,%2,%3};"
                 : "+f"(c[0]), "+f"(c[1]), "+f"(c[2]), "+f"(c[3])
                 : "r"(a0), "r"(a1), "r"(a2), "r"(a3), "r"(b0), "r"(b1));
}

// ---------------------------------------------------------------------------
// Kernel 1: head-pair split.  Block = (b, 16-row tile, head-pair), grid 256.
// 256 threads = (hh 2) x (rg 2 row-groups of 8) x (d 64).
// ---------------------------------------------------------------------------
#define K1_HST  0                      // [256 f][20]
#define K1_WHT  5120                   // [2 hh][64 k][20]
#define K1_EIT  7680
#define K1_EJT  10240
#define K1_FLOATS 12800
#define K1_BYTES  (K1_FLOATS*4)        // 51200

__global__ __launch_bounds__(256) void k1_proj(
    const float* __restrict__ hin, const float* __restrict__ W,
    const float* __restrict__ We1, const float* __restrict__ be1,
    const float* __restrict__ Wa1, const float* __restrict__ ba1)
{
    extern __shared__ __align__(16) float s1[];
    int bx = blockIdx.x;
    int b  = bx >> 5;
    int nt = (bx >> 1) & 15;
    int hp = bx & 1;
    int n0 = nt * 16;
    int tid = threadIdx.x;
    int hh  = tid >> 7;          // 0..1
    int rg  = (tid >> 6) & 1;    // 0..1
    int d   = tid & 63;
    int head = hp*2 + hh;
    int r0  = rg * 8;

    // stage h transposed: hst[f][nn], f = tid
#pragma unroll
    for (int nn = 0; nn < 16; ++nn)
        s1[K1_HST + tid*20 + nn] = hin[((size_t)(b*NN + n0 + nn))*FIN + tid];
    __syncthreads();

    float accW[8], accE1[8], accE2[8];
#pragma unroll
    for (int q = 0; q < 8; ++q) { accW[q]=0.f; accE1[q]=0.f; accE2[q]=0.f; }

#pragma unroll 4
    for (int f = 0; f < FIN; ++f) {
        float wv = W  [((size_t)head*FIN + f)*HD + d];
        float w1 = We1[((size_t)head*2*FIN + f)*HD + d];
        float w2 = We1[((size_t)head*2*FIN + FIN + f)*HD + d];
        float4 hA = *reinterpret_cast<const float4*>(&s1[K1_HST + f*20 + r0]);
        float4 hB = *reinterpret_cast<const float4*>(&s1[K1_HST + f*20 + r0 + 4]);
        accW [0] = fmaf(hA.x, wv, accW [0]); accW [1] = fmaf(hA.y, wv, accW [1]);
        accW [2] = fmaf(hA.z, wv, accW [2]); accW [3] = fmaf(hA.w, wv, accW [3]);
        accW [4] = fmaf(hB.x, wv, accW [4]); accW [5] = fmaf(hB.y, wv, accW [5]);
        accW [6] = fmaf(hB.z, wv, accW [6]); accW [7] = fmaf(hB.w, wv, accW [7]);
        accE1[0] = fmaf(hA.x, w1, accE1[0]); accE1[1] = fmaf(hA.y, w1, accE1[1]);
        accE1[2] = fmaf(hA.z, w1, accE1[2]); accE1[3] = fmaf(hA.w, w1, accE1[3]);
        accE1[4] = fmaf(hB.x, w1, accE1[4]); accE1[5] = fmaf(hB.y, w1, accE1[5]);
        accE1[6] = fmaf(hB.z, w1, accE1[6]); accE1[7] = fmaf(hB.w, w1, accE1[7]);
        accE2[0] = fmaf(hA.x, w2, accE2[0]); accE2[1] = fmaf(hA.y, w2, accE2[1]);
        accE2[2] = fmaf(hA.z, w2, accE2[2]); accE2[3] = fmaf(hA.w, w2, accE2[3]);
        accE2[4] = fmaf(hB.x, w2, accE2[4]); accE2[5] = fmaf(hB.y, w2, accE2[5]);
        accE2[6] = fmaf(hB.z, w2, accE2[6]); accE2[7] = fmaf(hB.w, w2, accE2[7]);
    }

    float bei = be1[head*HD + d];
    int tidx = (hh*64 + d)*20 + r0;
#pragma unroll
    for (int q = 0; q < 8; ++q) {
        size_t base = ((size_t)(b*NH + head)*NN + (n0 + r0 + q))*HD + d;
        float e1 = accE1[q] + bei;
        g_Wh[base] = accW[q];
        g_ei[base] = e1;
        g_ej[base] = accE2[q];
        s1[K1_WHT + tidx + q] = accW[q];
        s1[K1_EIT + tidx + q] = e1;
        s1[K1_EJT + tidx + q] = accE2[q];
    }
    __syncthreads();

    float accSi[8], accSj[8], accP[8], accQ[8];
#pragma unroll
    for (int q = 0; q < 8; ++q) { accSi[q]=0.f; accSj[q]=0.f; accP[q]=0.f; accQ[q]=0.f; }

#pragma unroll 2
    for (int k = 0; k < HD; ++k) {
        float wa = Wa1[((size_t)head*3*HD +        k)*HD + d];
        float wb = Wa1[((size_t)head*3*HD +   HD + k)*HD + d];
        float we = Wa1[((size_t)head*3*HD + 2*HD + k)*HD + d];
        int kb = (hh*64 + k)*20 + r0;
        float4 whA = *reinterpret_cast<const float4*>(&s1[K1_WHT + kb]);
        float4 whB = *reinterpret_cast<const float4*>(&s1[K1_WHT + kb + 4]);
        float4 eiA = *reinterpret_cast<const float4*>(&s1[K1_EIT + kb]);
        float4 eiB = *reinterpret_cast<const float4*>(&s1[K1_EIT + kb + 4]);
        float4 ejA = *reinterpret_cast<const float4*>(&s1[K1_EJT + kb]);
        float4 ejB = *reinterpret_cast<const float4*>(&s1[K1_EJT + kb + 4]);
        accSi[0] = fmaf(whA.x, wa, accSi[0]); accSi[1] = fmaf(whA.y, wa, accSi[1]);
        accSi[2] = fmaf(whA.z, wa, accSi[2]); accSi[3] = fmaf(whA.w, wa, accSi[3]);
        accSi[4] = fmaf(whB.x, wa, accSi[4]); accSi[5] = fmaf(whB.y, wa, accSi[5]);
        accSi[6] = fmaf(whB.z, wa, accSi[6]); accSi[7] = fmaf(whB.w, wa, accSi[7]);
        accSj[0] = fmaf(whA.x, wb, accSj[0]); accSj[1] = fmaf(whA.y, wb, accSj[1]);
        accSj[2] = fmaf(whA.z, wb, accSj[2]); accSj[3] = fmaf(whA.w, wb, accSj[3]);
        accSj[4] = fmaf(whB.x, wb, accSj[4]); accSj[5] = fmaf(whB.y, wb, accSj[5]);
        accSj[6] = fmaf(whB.z, wb, accSj[6]); accSj[7] = fmaf(whB.w, wb, accSj[7]);
        accP [0] = fmaf(eiA.x, we, accP [0]); accP [1] = fmaf(eiA.y, we, accP [1]);
        accP [2] = fmaf(eiA.z, we, accP [2]); accP [3] = fmaf(eiA.w, we, accP [3]);
        accP [4] = fmaf(eiB.x, we, accP [4]); accP [5] = fmaf(eiB.y, we, accP [5]);
        accP [6] = fmaf(eiB.z, we, accP [6]); accP [7] = fmaf(eiB.w, we, accP [7]);
        accQ [0] = fmaf(ejA.x, we, accQ [0]); accQ [1] = fmaf(ejA.y, we, accQ [1]);
        accQ [2] = fmaf(ejA.z, we, accQ [2]); accQ [3] = fmaf(ejA.w, we, accQ [3]);
        accQ [4] = fmaf(ejB.x, we, accQ [4]); accQ [5] = fmaf(ejB.y, we, accQ [5]);
        accQ [6] = fmaf(ejB.z, we, accQ [6]); accQ [7] = fmaf(ejB.w, we, accQ [7]);
    }
    float bsi = ba1[head*HD + d];
#pragma unroll
    for (int q = 0; q < 8; ++q) {
        size_t base = ((size_t)(b*NH + head)*NN + (n0 + r0 + q))*HD + d;
        g_si2[base] = accSi[q] + bsi + 0.6f*accP[q];
        g_sj2[base] = accSj[q]       + 0.6f*accQ[q];
    }
}

// ---------------------------------------------------------------------------
// t2f: fused edge GEMM (bf16 mma) + softmax + hp + layernorm.
// R5 version: 512 threads = 16 warps (each: 16 j-rows, full d).
// ---------------------------------------------------------------------------
#define O_EJ   0                       // uint32[256*36]  (bf16x2 ej, pitch 36 words)
#define O_SJ   9216                    // float[256*68]
#define O_WH   26624                   // float[256*68]
#define O_WEB  44032                   // uint32[32*64]   (bf16x2 0.4*We pairs)
#define O_EI   46080                   // uint32[16*32]   (bf16x2 ei)
#define O_SI   46592                   // float[16*64]
#define O_WA2  47616                   // float[64]
#define O_ET   47680                   // float[256*18]   ([j][i])
#define O_HP   52288                   // float[16*68]
#define T2_FLOATS 53376
#define T2_BYTES  (T2_FLOATS*4)        // 213504

__global__ __launch_bounds__(512) void t2f(
    const float* __restrict__ Wa1, const float* __restrict__ wa2,
    const int*   __restrict__ adj, const float* __restrict__ ba2,
    const float* __restrict__ ln_g, const float* __restrict__ ln_b)
{
    extern __shared__ __align__(16) float sm[];
    uint32_t* smu = reinterpret_cast<uint32_t*>(sm);

    int bx   = blockIdx.x;
    int it   = bx & 15;
    int head = (bx >> 4) & 3;
    int b    = bx >> 6;
    int i0   = it * 16;
    int tid  = threadIdx.x;
    int wid  = tid >> 5, lane = tid & 31;
    int gid  = lane >> 2, tig = lane & 3;

    size_t bh = (size_t)(b*NH + head);

    // ---- staging ----
    for (int t = tid; t < NN*32; t += 512) {           // EJ -> bf16x2
        int j = t >> 5, kk = t & 31;
        float2 v = *reinterpret_cast<const float2*>(&g_ej[(bh*NN + j)*HD + 2*kk]);
        smu[O_EJ + j*36 + kk] = packbf(v.x, v.y);
    }
    for (int t = tid*4; t < NN*HD; t += 512*4) {       // SJ, WH fp32
        int j = t >> 6, k = t & 63;
        *reinterpret_cast<float4*>(&sm[O_SJ + j*68 + k]) =
            *reinterpret_cast<const float4*>(&g_sj2[(bh*NN + j)*HD + k]);
        *reinterpret_cast<float4*>(&sm[O_WH + j*68 + k]) =
            *reinterpret_cast<const float4*>(&g_Wh[(bh*NN + j)*HD + k]);
    }
    for (int t = tid; t < 32*64; t += 512) {           // WEB: 0.4*We bf16 pairs
        int kk = t >> 6, d = t & 63;
        float f0 = 0.4f * Wa1[((size_t)head*3*HD + 2*HD + 2*kk    )*HD + d];
        float f1 = 0.4f * Wa1[((size_t)head*3*HD + 2*HD + 2*kk + 1)*HD + d];
        smu[O_WEB + t] = packbf(f0, f1);
    }
    for (int t = tid; t < 16*32; t += 512) {           // EI -> bf16x2
        int ii = t >> 5, kk = t & 31;
        float2 v = *reinterpret_cast<const float2*>(&g_ei[(bh*NN + i0 + ii)*HD + 2*kk]);
        smu[O_EI + t] = packbf(v.x, v.y);
    }
    for (int t = tid; t < 16*64; t += 512) {           // SI fp32
        int ii = t >> 6, d = t & 63;
        sm[O_SI + t] = g_si2[(bh*NN + i0 + ii)*HD + d];
    }
    if (tid < 64) sm[O_WA2 + tid] = wa2[head*HD + tid];
    __syncthreads();

    // ---- resident B fragments ----
    uint32_t bfr[4][8][2];
#pragma unroll
    for (int ks = 0; ks < 4; ++ks)
#pragma unroll
        for (int nt = 0; nt < 8; ++nt) {
            int d = nt*8 + gid;
            bfr[ks][nt][0] = smu[O_WEB + (ks*8 + tig    )*64 + d];
            bfr[ks][nt][1] = smu[O_WEB + (ks*8 + tig + 4)*64 + d];
        }

    // ---- edge phase: warp owns j rows [wid*16, wid*16+16) ----
    int j0 = wid*16;
    int r0 = j0 + gid, r1 = r0 + 8;

    for (int ii = 0; ii < 16; ++ii) {
        uint32_t eir[8];
#pragma unroll
        for (int ks = 0; ks < 4; ++ks) {
            eir[2*ks]   = smu[O_EI + ii*32 + ks*8 + tig];
            eir[2*ks+1] = smu[O_EI + ii*32 + ks*8 + 4 + tig];
        }
        float acc[8][4];
#pragma unroll
        for (int nt = 0; nt < 8; ++nt) {
            float2 s = *reinterpret_cast<const float2*>(&sm[O_SI + ii*64 + nt*8 + 2*tig]);
            acc[nt][0] = s.x; acc[nt][1] = s.y; acc[nt][2] = s.x; acc[nt][3] = s.y;
        }
#pragma unroll
        for (int ks = 0; ks < 4; ++ks) {
            uint32_t e0 = smu[O_EJ + r0*36 + ks*8 + tig];
            uint32_t e1 = smu[O_EJ + r1*36 + ks*8 + tig];
            uint32_t e2 = smu[O_EJ + r0*36 + ks*8 + 4 + tig];
            uint32_t e3 = smu[O_EJ + r1*36 + ks*8 + 4 + tig];
            uint32_t a0 = habs2(hadd2(e0, eir[2*ks]));
            uint32_t a1 = habs2(hadd2(e1, eir[2*ks]));
            uint32_t a2 = habs2(hadd2(e2, eir[2*ks+1]));
            uint32_t a3 = habs2(hadd2(e3, eir[2*ks+1]));
#pragma unroll
            for (int nt = 0; nt < 8; ++nt)
                mma16816(acc[nt], a0, a1, a2, a3, bfr[ks][nt][0], bfr[ks][nt][1]);
        }
        // epilogue: e[i, r0], e[i, r1]
        float pe0 = 0.f, pe1 = 0.f;
#pragma unroll
        for (int nt = 0; nt < 8; ++nt) {
            int d = nt*8 + 2*tig;
            float2 sj0 = *reinterpret_cast<const float2*>(&sm[O_SJ + r0*68 + d]);
            float2 sj1 = *reinterpret_cast<const float2*>(&sm[O_SJ + r1*68 + d]);
            float2 w2  = *reinterpret_cast<const float2*>(&sm[O_WA2 + d]);
            float v00 = acc[nt][0] + sj0.x, v01 = acc[nt][1] + sj0.y;
            float v10 = acc[nt][2] + sj1.x, v11 = acc[nt][3] + sj1.y;
            pe0 = fmaf(fmaxf(v00, ALPHA*v00), w2.x, pe0);
            pe0 = fmaf(fmaxf(v01, ALPHA*v01), w2.y, pe0);
            pe1 = fmaf(fmaxf(v10, ALPHA*v10), w2.x, pe1);
            pe1 = fmaf(fmaxf(v11, ALPHA*v11), w2.y, pe1);
        }
        pe0 += __shfl_xor_sync(0xffffffffu, pe0, 1);
        pe0 += __shfl_xor_sync(0xffffffffu, pe0, 2);
        pe1 += __shfl_xor_sync(0xffffffffu, pe1, 1);
        pe1 += __shfl_xor_sync(0xffffffffu, pe1, 2);
        if (tig == 0) {
            sm[O_ET + r0*18 + ii] = pe0;
            sm[O_ET + r1*18 + ii] = pe1;
        }
    }
    __syncthreads();

    // ---- masked softmax: warp wid handles i = wid ----
    {
        int i = wid;
        int iglob = i0 + i;
        float bav = ba2[head];
        float vals[8]; float mx = -1e30f;
#pragma unroll
        for (int s = 0; s < 8; ++s) {
            int j = lane + 32*s;
            float pe = sm[O_ET + j*18 + i] + bav;
            int a = adj[((size_t)b*NN + iglob)*NN + j];
            vals[s] = (a == 0) ? -1e9f : pe;
            mx = fmaxf(mx, vals[s]);
        }
#pragma unroll
        for (int o = 16; o; o >>= 1) mx = fmaxf(mx, __shfl_xor_sync(0xffffffffu, mx, o));
        float se = 0.f;
#pragma unroll
        for (int s = 0; s < 8; ++s) { vals[s] = __expf(vals[s] - mx); se += vals[s]; }
#pragma unroll
        for (int o = 16; o; o >>= 1) se += __shfl_xor_sync(0xffffffffu, se, o);
        float inv = 1.0f / se;
#pragma unroll
        for (int s = 0; s < 8; ++s)
            sm[O_ET + (lane + 32*s)*18 + i] = vals[s] * inv;
    }
    __syncthreads();

    // ---- hp[i][d] = sum_j attn[i][j] * Wh[j][d]   (f32x2 over i-pairs) ----
    {
        int d = tid & 63, ig = tid >> 6;          // ig 0..7 -> i pair {2ig, 2ig+1}
        unsigned long long acc2 = 0ull;
#pragma unroll 4
        for (int j = 0; j < NN; ++j) {
            float wh = sm[O_WH + j*68 + d];
            unsigned long long at = *reinterpret_cast<const unsigned long long*>(&sm[O_ET + j*18 + 2*ig]);
            fma2(acc2, at, pack2(wh));
        }
        float h0, h1; unpack2(acc2, h0, h1);
        sm[O_HP + (2*ig    )*68 + d] = h0;
        sm[O_HP + (2*ig + 1)*68 + d] = h1;
    }
    __syncthreads();

    // ---- per-head layernorm: warp wid handles i = wid ----
    {
        int i = wid;
        float x0 = sm[O_HP + i*68 + lane];
        float x1 = sm[O_HP + i*68 + 32 + lane];
        float s1 = x0 + x1, s2 = x0*x0 + x1*x1;
#pragma unroll
        for (int o = 16; o; o >>= 1) {
            s1 += __shfl_xor_sync(0xffffffffu, s1, o);
            s2 += __shfl_xor_sync(0xffffffffu, s2, o);
        }
        float m   = s1 * (1.0f/64.0f);
        float var = s2 * (1.0f/64.0f) - m*m;
        float r   = rsqrtf(var + 1e-5f);
        size_t obase = ((size_t)(b*NN) + i0 + i)*FIN + head*HD;
        g_concat[obase + lane]      = (x0 - m)*r*ln_g[head*HD + lane]      + ln_b[head*HD + lane];
        g_concat[obase + 32 + lane] = (x1 - m)*r*ln_g[head*HD + 32 + lane] + ln_b[head*HD + 32 + lane];
    }
}

// ---------------------------------------------------------------------------
// Kernel 3: NT=8, grid 256, transposed pitch-12 staging, fused LN.
// ---------------------------------------------------------------------------
__global__ __launch_bounds__(256) void k3_out(
    const float* __restrict__ hin, const float* __restrict__ Wo,
    const float* __restrict__ bo,  const float* __restrict__ g2,
    const float* __restrict__ b2,  float* __restrict__ out)
{
    const int NT = 8;
    int b  = blockIdx.x >> 5;
    int n0 = (blockIdx.x & 31) * NT;
    int tid = threadIdx.x;

    __shared__ __align__(16) float cst[FIN*12];   // transposed, pitch 12
    __shared__ float hs2[NT][FIN];

#pragma unroll
    for (int nn = 0; nn < NT; ++nn) {
        cst[tid*12 + nn] = g_concat[((size_t)b*NN + n0 + nn)*FIN + tid];
        hs2[nn][tid]     = hin     [((size_t)b*NN + n0 + nn)*FIN + tid];
    }
    __syncthreads();

    float bv = bo[tid];
    float acc[NT];
#pragma unroll
    for (int nn = 0; nn < NT; ++nn) acc[nn] = bv;

#pragma unroll 4
    for (int f = 0; f < FIN; ++f) {
        float w = Wo[(size_t)f*FIN + tid];
        float4 cA = *reinterpret_cast<const float4*>(&cst[f*12]);
        float4 cB = *reinterpret_cast<const float4*>(&cst[f*12 + 4]);
        acc[0] = fmaf(cA.x, w, acc[0]); acc[1] = fmaf(cA.y, w, acc[1]);
        acc[2] = fmaf(cA.z, w, acc[2]); acc[3] = fmaf(cA.w, w, acc[3]);
        acc[4] = fmaf(cB.x, w, acc[4]); acc[5] = fmaf(cB.y, w, acc[5]);
        acc[6] = fmaf(cB.z, w, acc[6]); acc[7] = fmaf(cB.w, w, acc[7]);
    }
    __syncthreads();
#pragma unroll
    for (int nn = 0; nn < NT; ++nn)
        hs2[nn][tid] = acc[nn] + hs2[nn][tid];
    __syncthreads();

    // layernorm: one warp per row
    int wid = tid >> 5, lane = tid & 31;
    float s1 = 0.f, s2 = 0.f;
#pragma unroll
    for (int k = 0; k < 8; ++k) {
        float x = hs2[wid][k*32 + lane];
        s1 += x; s2 += x*x;
    }
#pragma unroll
    for (int o = 16; o; o >>= 1) {
        s1 += __shfl_xor_sync(0xffffffffu, s1, o);
        s2 += __shfl_xor_sync(0xffffffffu, s2, o);
    }
    float m   = s1 * (1.0f/256.0f);
    float var = s2 * (1.0f/256.0f) - m*m;
    float rr  = rsqrtf(var + 1e-5f);
#pragma unroll
    for (int k = 0; k < 8; ++k) {
        int c = k*32 + lane;
        float x = hs2[wid][c];
        out[((size_t)b*NN + n0 + wid)*FIN + c] = (x - m)*rr*g2[c] + b2[c];
    }
}

// ---------------------------------------------------------------------------
extern "C" void kernel_launch(void* const* d_in, const int* in_sizes, int n_in,
                              void* d_out, int out_size)
{
    const float* h    = (const float*)d_in[0];
    const int*   adj  = (const int*)  d_in[1];
    const float* W    = (const float*)d_in[2];
    const float* We1  = (const float*)d_in[3];
    const float* be1  = (const float*)d_in[4];
    const float* Wa1  = (const float*)d_in[5];
    const float* ba1  = (const float*)d_in[6];
    const float* wa2  = (const float*)d_in[7];
    const float* ba2  = (const float*)d_in[8];
    const float* ln_g = (const float*)d_in[9];
    const float* ln_b = (const float*)d_in[10];
    const float* Wo   = (const float*)d_in[11];
    const float* bo   = (const float*)d_in[12];
    const float* g2   = (const float*)d_in[13];
    const float* b2   = (const float*)d_in[14];
    float* out = (float*)d_out;

    cudaFuncSetAttribute(k1_proj, cudaFuncAttributeMaxDynamicSharedMemorySize, K1_BYTES);
    cudaFuncSetAttribute(t2f,     cudaFuncAttributeMaxDynamicSharedMemorySize, T2_BYTES);

    k1_proj<<<NB*(NN/16)*2, 256, K1_BYTES>>>(h, W, We1, be1, Wa1, ba1);
    t2f    <<<NB*NH*(NN/16), 512, T2_BYTES>>>(Wa1, wa2, adj, ba2, ln_g, ln_b);
    k3_out <<<NB*(NN/8), 256>>>(h, Wo, bo, g2, b2, out);
}

// round 10
// speedup vs baseline: 1.1030x; 1.0387x over previous
#include <cuda_runtime.h>
#include <math.h>
#include <stdint.h>

#define NB   8
#define NN   256
#define NH   4
#define HD   64
#define FIN  256
#define ALPHA 0.2f

// ---------------- scratch (__device__ globals; no allocs allowed) ----------
__device__ float g_Wh [NB*NH*NN*HD];
__device__ float g_si2[NB*NH*NN*HD];   // si + ba1 + 0.6*(ei@We)
__device__ float g_sj2[NB*NH*NN*HD];   // sj + 0.6*(ej@We)
__device__ float g_ei [NB*NH*NN*HD];
__device__ float g_ej [NB*NH*NN*HD];
__device__ float g_concat[NB*NN*FIN];

// ---------------- packed helpers -------------------------------------------
__device__ __forceinline__ unsigned long long pack2(float v) {
    unsigned long long r; unsigned u = __float_as_uint(v);
    asm("mov.b64 %0, {%1, %1};" : "=l"(r) : "r"(u));
    return r;
}
__device__ __forceinline__ void fma2(unsigned long long& d,
                                     unsigned long long a, unsigned long long b) {
    asm("fma.rn.f32x2 %0, %1, %2, %0;" : "+l"(d) : "l"(a), "l"(b));
}
__device__ __forceinline__ void unpack2(unsigned long long v, float& lo, float& hi) {
    unsigned a, b;
    asm("mov.b64 {%0, %1}, %2;" : "=r"(a), "=r"(b) : "l"(v));
    lo = __uint_as_float(a); hi = __uint_as_float(b);
}
__device__ __forceinline__ uint32_t packbf(float lo, float hi) {   // low half = lo
    uint32_t r;
    asm("cvt.rn.bf16x2.f32 %0, %1, %2;" : "=r"(r) : "f"(hi), "f"(lo));
    return r;
}
__device__ __forceinline__ uint32_t hadd2(uint32_t a, uint32_t b) {
    uint32_t r;
    asm("add.rn.bf16x2 %0, %1, %2;" : "=r"(r) : "r"(a), "r"(b));
    return r;
}
__device__ __forceinline__ uint32_t habs2(uint32_t a) { return a & 0x7FFF7FFFu; }

__device__ __forceinline__ void mma16816(float* c, uint32_t a0, uint32_t a1,
                                         uint32_t a2, uint32_t a3,
                                         uint32_t b0, uint32_t b1) {
    asm volatile("mma.sync.aligned.m16n8k16.row.col.f32.bf16.bf16.f32 "
                 "{%0,%1,%2,%3}, {%4,%5,%6,%7}, {%8,%9}, {%0,%1,%2,%3};"
                 : "+f"(c[0]), "+f"(c[1]), "+f"(c[2]), "+f"(c[3])
                 : "r"(a0), "r"(a1), "r"(a2), "r"(a3), "r"(b0), "r"(b1));
}

// ---- tf32 mma helpers (fragment layout verified in R4) ----
__device__ __forceinline__ uint32_t cvt_tf32(float x) {
    uint32_t r; asm("cvt.rna.tf32.f32 %0, %1;" : "=r"(r) : "f"(x)); return r;
}
__device__ __forceinline__ float cvt_tf32f(float x) {
    return __uint_as_float(cvt_tf32(x));
}
__device__ __forceinline__ void mma1688(float* c, uint32_t a0, uint32_t a1,
                                        uint32_t a2, uint32_t a3,
                                        uint32_t b0, uint32_t b1) {
    asm volatile("mma.sync.aligned.m16n8k8.row.col.f32.tf32.tf32.f32 "
                 "{%0,%1,%2,%3}, {%4,%5,%6,%7}, {%8,%9}, {%0,%1,%2,%3};"
                 : "+f"(c[0]), "+f"(c[1]), "+f"(c[2]), "+f"(c[3])
                 : "r"(a0), "r"(a1), "r"(a2), "r"(a3), "r"(b0), "r"(b1));
}

// ---------------------------------------------------------------------------
// Kernel 1 (tf32 tensor-core): block = (b, 16-row tile), grid 128, 256 thr.
// Phase A: [16 x 768] = hT @ [W | We1a | We1b]  (cols = mat*256 + head*64 + d)
// Phase B: per (head, si|sj): [16 x 64], K=128 = [Wh | ei_or_ej] @ [Wx ; 0.6We]
// ---------------------------------------------------------------------------
#define K1_HST 0                        // [256 k][24]  (tf32-rounded h, transposed)
#define K1_TR  6144                     // [head][mat(wh,ei,ej)][64 k][24]
#define K1_FLOATS (6144 + 4*3*64*24)    // 24576
#define K1_BYTES  (K1_FLOATS*4)         // 98304

__global__ __launch_bounds__(256) void k1_proj(
    const float* __restrict__ hin, const float* __restrict__ W,
    const float* __restrict__ We1, const float* __restrict__ be1,
    const float* __restrict__ Wa1, const float* __restrict__ ba1)
{
    extern __shared__ __align__(16) float s1[];
    int b  = blockIdx.x >> 4;
    int n0 = (blockIdx.x & 15) * 16;
    int tid = threadIdx.x;
    int wid = tid >> 5, lane = tid & 31;
    int gid = lane >> 2, tig = lane & 3;

    // ---- stage h transposed, tf32-rounded: hst[f][row], pitch 24 ----
    {
        const float* hrow = hin + ((size_t)b*NN + n0)*FIN + tid;
#pragma unroll
        for (int r = 0; r < 16; ++r)
            s1[K1_HST + tid*24 + r] = cvt_tf32f(hrow[(size_t)r*FIN]);
    }
    __syncthreads();

    // ---- phase A ----
    const float* wp[12];
#pragma unroll
    for (int nt = 0; nt < 12; ++nt) {
        int ntg = wid*12 + nt;
        int mat = ntg >> 5, rem = ntg & 31;
        int head = rem >> 3, d0 = (rem & 7)*8;
        const float* base = (mat == 0)
            ? (W + (size_t)head*FIN*HD)
            : (We1 + (size_t)head*2*FIN*HD + (size_t)(mat-1)*FIN*HD);
        wp[nt] = base + d0 + gid;
    }

    float acc[12][4];
#pragma unroll
    for (int nt = 0; nt < 12; ++nt)
        acc[nt][0]=acc[nt][1]=acc[nt][2]=acc[nt][3]=0.f;

#pragma unroll 2
    for (int k0 = 0; k0 < FIN; k0 += 8) {
        uint32_t a0 = __float_as_uint(s1[K1_HST + (k0+tig)*24 + gid]);
        uint32_t a1 = __float_as_uint(s1[K1_HST + (k0+tig)*24 + gid + 8]);
        uint32_t a2 = __float_as_uint(s1[K1_HST + (k0+tig+4)*24 + gid]);
        uint32_t a3 = __float_as_uint(s1[K1_HST + (k0+tig+4)*24 + gid + 8]);
        int off0 = (k0+tig)*HD, off1 = (k0+tig+4)*HD;
#pragma unroll
        for (int nt = 0; nt < 12; ++nt) {
            uint32_t b0 = cvt_tf32(wp[nt][off0]);
            uint32_t b1 = cvt_tf32(wp[nt][off1]);
            mma1688(acc[nt], a0, a1, a2, a3, b0, b1);
        }
    }

    // epilogue A: write fp32 to global, tf32 to smem (transposed for phase B)
#pragma unroll
    for (int nt = 0; nt < 12; ++nt) {
        int ntg = wid*12 + nt;
        int mat = ntg >> 5, rem = ntg & 31;
        int head = rem >> 3, d0 = (rem & 7)*8;
        int c0 = d0 + 2*tig;
        float v00 = acc[nt][0], v01 = acc[nt][1], v10 = acc[nt][2], v11 = acc[nt][3];
        if (mat == 1) {
            float e0 = be1[head*HD + c0], e1 = be1[head*HD + c0 + 1];
            v00 += e0; v01 += e1; v10 += e0; v11 += e1;
        }
        float* gout = (mat == 0) ? g_Wh : ((mat == 1) ? g_ei : g_ej);
        size_t rbase = ((size_t)(b*NH + head)*NN + n0);
        *reinterpret_cast<float2*>(&gout[(rbase + gid)*HD + c0])     = make_float2(v00, v01);
        *reinterpret_cast<float2*>(&gout[(rbase + gid + 8)*HD + c0]) = make_float2(v10, v11);
        int tb = K1_TR + (head*3 + mat)*64*24;
        s1[tb + (c0    )*24 + gid    ] = cvt_tf32f(v00);
        s1[tb + (c0 + 1)*24 + gid    ] = cvt_tf32f(v01);
        s1[tb + (c0    )*24 + gid + 8] = cvt_tf32f(v10);
        s1[tb + (c0 + 1)*24 + gid + 8] = cvt_tf32f(v11);
    }
    __syncthreads();

    // ---- phase B: warp = (head, si|sj) ----
    {
        int head  = wid >> 1, which = wid & 1;
        int trb   = K1_TR + head*3*64*24;            // wh block
        int hib   = trb + (which ? 1536 : 0);        // hi half: ei (si) or ej (sj); +k*24 with k>=64
        const float* wb_lo = Wa1 + ((size_t)head*3*HD + which*HD)*HD;   // Wa or Wb
        const float* wb_hi = Wa1 + ((size_t)head*3*HD + 2*HD)*HD;       // We

        float acc2[8][4];
#pragma unroll
        for (int nt = 0; nt < 8; ++nt)
            acc2[nt][0]=acc2[nt][1]=acc2[nt][2]=acc2[nt][3]=0.f;

        // k 0..63: Wh @ (Wa|Wb)
#pragma unroll 2
        for (int ks = 0; ks < 8; ++ks) {
            int k0 = ks*8;
            uint32_t a0 = __float_as_uint(s1[trb + (k0+tig)*24 + gid]);
            uint32_t a1 = __float_as_uint(s1[trb + (k0+tig)*24 + gid + 8]);
            uint32_t a2 = __float_as_uint(s1[trb + (k0+tig+4)*24 + gid]);
            uint32_t a3 = __float_as_uint(s1[trb + (k0+tig+4)*24 + gid + 8]);
#pragma unroll
            for (int nt = 0; nt < 8; ++nt) {
                uint32_t b0 = cvt_tf32(wb_lo[(k0+tig)*HD + nt*8 + gid]);
                uint32_t b1 = cvt_tf32(wb_lo[(k0+tig+4)*HD + nt*8 + gid]);
                mma1688(acc2[nt], a0, a1, a2, a3, b0, b1);
            }
        }
        // k 64..127: (ei|ej) @ 0.6*We
#pragma unroll 2
        for (int ks = 0; ks < 8; ++ks) {
            int k0 = ks*8;
            uint32_t a0 = __float_as_uint(s1[hib + (k0+64+tig)*24 + gid]);
            uint32_t a1 = __float_as_uint(s1[hib + (k0+64+tig)*24 + gid + 8]);
            uint32_t a2 = __float_as_uint(s1[hib + (k0+64+tig+4)*24 + gid]);
            uint32_t a3 = __float_as_uint(s1[hib + (k0+64+tig+4)*24 + gid + 8]);
#pragma unroll
            for (int nt = 0; nt < 8; ++nt) {
                uint32_t b0 = cvt_tf32(0.6f * wb_hi[(k0+tig)*HD + nt*8 + gid]);
                uint32_t b1 = cvt_tf32(0.6f * wb_hi[(k0+tig+4)*HD + nt*8 + gid]);
                mma1688(acc2[nt], a0, a1, a2, a3, b0, b1);
            }
        }
        // epilogue B
#pragma unroll
        for (int nt = 0; nt < 8; ++nt) {
            int c0 = nt*8 + 2*tig;
            float v00=acc2[nt][0], v01=acc2[nt][1], v10=acc2[nt][2], v11=acc2[nt][3];
            if (which == 0) {
                float b0v = ba1[head*HD + c0], b1v = ba1[head*HD + c0 + 1];
                v00 += b0v; v01 += b1v; v10 += b0v; v11 += b1v;
            }
            float* gout = which == 0 ? g_si2 : g_sj2;
            size_t rbase = ((size_t)(b*NH + head)*NN + n0);
            *reinterpret_cast<float2*>(&gout[(rbase + gid)*HD + c0])     = make_float2(v00, v01);
            *reinterpret_cast<float2*>(&gout[(rbase + gid + 8)*HD + c0]) = make_float2(v10, v11);
        }
    }
}

// ---------------------------------------------------------------------------
// t2f: fused edge GEMM (bf16 mma) + softmax + hp + layernorm.
// R9 version (unchanged): 512 threads = 16 warps.
// ---------------------------------------------------------------------------
#define O_EJ   0
#define O_SJ   9216
#define O_WH   26624
#define O_WEB  44032
#define O_EI   46080
#define O_SI   46592
#define O_WA2  47616
#define O_ET   47680
#define O_HP   52288
#define T2_FLOATS 53376
#define T2_BYTES  (T2_FLOATS*4)

__global__ __launch_bounds__(512) void t2f(
    const float* __restrict__ Wa1, const float* __restrict__ wa2,
    const int*   __restrict__ adj, const float* __restrict__ ba2,
    const float* __restrict__ ln_g, const float* __restrict__ ln_b)
{
    extern __shared__ __align__(16) float sm[];
    uint32_t* smu = reinterpret_cast<uint32_t*>(sm);

    int bx   = blockIdx.x;
    int it   = bx & 15;
    int head = (bx >> 4) & 3;
    int b    = bx >> 6;
    int i0   = it * 16;
    int tid  = threadIdx.x;
    int wid  = tid >> 5, lane = tid & 31;
    int gid  = lane >> 2, tig = lane & 3;

    size_t bh = (size_t)(b*NH + head);

    for (int t = tid; t < NN*32; t += 512) {
        int j = t >> 5, kk = t & 31;
        float2 v = *reinterpret_cast<const float2*>(&g_ej[(bh*NN + j)*HD + 2*kk]);
        smu[O_EJ + j*36 + kk] = packbf(v.x, v.y);
    }
    for (int t = tid*4; t < NN*HD; t += 512*4) {
        int j = t >> 6, k = t & 63;
        *reinterpret_cast<float4*>(&sm[O_SJ + j*68 + k]) =
            *reinterpret_cast<const float4*>(&g_sj2[(bh*NN + j)*HD + k]);
        *reinterpret_cast<float4*>(&sm[O_WH + j*68 + k]) =
            *reinterpret_cast<const float4*>(&g_Wh[(bh*NN + j)*HD + k]);
    }
    for (int t = tid; t < 32*64; t += 512) {
        int kk = t >> 6, d = t & 63;
        float f0 = 0.4f * Wa1[((size_t)head*3*HD + 2*HD + 2*kk    )*HD + d];
        float f1 = 0.4f * Wa1[((size_t)head*3*HD + 2*HD + 2*kk + 1)*HD + d];
        smu[O_WEB + t] = packbf(f0, f1);
    }
    for (int t = tid; t < 16*32; t += 512) {
        int ii = t >> 5, kk = t & 31;
        float2 v = *reinterpret_cast<const float2*>(&g_ei[(bh*NN + i0 + ii)*HD + 2*kk]);
        smu[O_EI + t] = packbf(v.x, v.y);
    }
    for (int t = tid; t < 16*64; t += 512) {
        int ii = t >> 6, d = t & 63;
        sm[O_SI + t] = g_si2[(bh*NN + i0 + ii)*HD + d];
    }
    if (tid < 64) sm[O_WA2 + tid] = wa2[head*HD + tid];
    __syncthreads();

    uint32_t bfr[4][8][2];
#pragma unroll
    for (int ks = 0; ks < 4; ++ks)
#pragma unroll
        for (int nt = 0; nt < 8; ++nt) {
            int d = nt*8 + gid;
            bfr[ks][nt][0] = smu[O_WEB + (ks*8 + tig    )*64 + d];
            bfr[ks][nt][1] = smu[O_WEB + (ks*8 + tig + 4)*64 + d];
        }

    int j0 = wid*16;
    int r0 = j0 + gid, r1 = r0 + 8;

    for (int ii = 0; ii < 16; ++ii) {
        uint32_t eir[8];
#pragma unroll
        for (int ks = 0; ks < 4; ++ks) {
            eir[2*ks]   = smu[O_EI + ii*32 + ks*8 + tig];
            eir[2*ks+1] = smu[O_EI + ii*32 + ks*8 + 4 + tig];
        }
        float acc[8][4];
#pragma unroll
        for (int nt = 0; nt < 8; ++nt) {
            float2 s = *reinterpret_cast<const float2*>(&sm[O_SI + ii*64 + nt*8 + 2*tig]);
            acc[nt][0] = s.x; acc[nt][1] = s.y; acc[nt][2] = s.x; acc[nt][3] = s.y;
        }
#pragma unroll
        for (int ks = 0; ks < 4; ++ks) {
            uint32_t e0 = smu[O_EJ + r0*36 + ks*8 + tig];
            uint32_t e1 = smu[O_EJ + r1*36 + ks*8 + tig];
            uint32_t e2 = smu[O_EJ + r0*36 + ks*8 + 4 + tig];
            uint32_t e3 = smu[O_EJ + r1*36 + ks*8 + 4 + tig];
            uint32_t a0 = habs2(hadd2(e0, eir[2*ks]));
            uint32_t a1 = habs2(hadd2(e1, eir[2*ks]));
            uint32_t a2 = habs2(hadd2(e2, eir[2*ks+1]));
            uint32_t a3 = habs2(hadd2(e3, eir[2*ks+1]));
#pragma unroll
            for (int nt = 0; nt < 8; ++nt)
                mma16816(acc[nt], a0, a1, a2, a3, bfr[ks][nt][0], bfr[ks][nt][1]);
        }
        float pe0 = 0.f, pe1 = 0.f;
#pragma unroll
        for (int nt = 0; nt < 8; ++nt) {
            int d = nt*8 + 2*tig;
            float2 sj0 = *reinterpret_cast<const float2*>(&sm[O_SJ + r0*68 + d]);
            float2 sj1 = *reinterpret_cast<const float2*>(&sm[O_SJ + r1*68 + d]);
            float2 w2  = *reinterpret_cast<const float2*>(&sm[O_WA2 + d]);
            float v00 = acc[nt][0] + sj0.x, v01 = acc[nt][1] + sj0.y;
            float v10 = acc[nt][2] + sj1.x, v11 = acc[nt][3] + sj1.y;
            pe0 = fmaf(fmaxf(v00, ALPHA*v00), w2.x, pe0);
            pe0 = fmaf(fmaxf(v01, ALPHA*v01), w2.y, pe0);
            pe1 = fmaf(fmaxf(v10, ALPHA*v10), w2.x, pe1);
            pe1 = fmaf(fmaxf(v11, ALPHA*v11), w2.y, pe1);
        }
        pe0 += __shfl_xor_sync(0xffffffffu, pe0, 1);
        pe0 += __shfl_xor_sync(0xffffffffu, pe0, 2);
        pe1 += __shfl_xor_sync(0xffffffffu, pe1, 1);
        pe1 += __shfl_xor_sync(0xffffffffu, pe1, 2);
        if (tig == 0) {
            sm[O_ET + r0*18 + ii] = pe0;
            sm[O_ET + r1*18 + ii] = pe1;
        }
    }
    __syncthreads();

    {
        int i = wid;
        int iglob = i0 + i;
        float bav = ba2[head];
        float vals[8]; float mx = -1e30f;
#pragma unroll
        for (int s = 0; s < 8; ++s) {
            int j = lane + 32*s;
            float pe = sm[O_ET + j*18 + i] + bav;
            int a = adj[((size_t)b*NN + iglob)*NN + j];
            vals[s] = (a == 0) ? -1e9f : pe;
            mx = fmaxf(mx, vals[s]);
        }
#pragma unroll
        for (int o = 16; o; o >>= 1) mx = fmaxf(mx, __shfl_xor_sync(0xffffffffu, mx, o));
        float se = 0.f;
#pragma unroll
        for (int s = 0; s < 8; ++s) { vals[s] = __expf(vals[s] - mx); se += vals[s]; }
#pragma unroll
        for (int o = 16; o; o >>= 1) se += __shfl_xor_sync(0xffffffffu, se, o);
        float inv = 1.0f / se;
#pragma unroll
        for (int s = 0; s < 8; ++s)
            sm[O_ET + (lane + 32*s)*18 + i] = vals[s] * inv;
    }
    __syncthreads();

    {
        int d = tid & 63, ig = tid >> 6;
        unsigned long long acc2 = 0ull;
#pragma unroll 4
        for (int j = 0; j < NN; ++j) {
            float wh = sm[O_WH + j*68 + d];
            unsigned long long at = *reinterpret_cast<const unsigned long long*>(&sm[O_ET + j*18 + 2*ig]);
            fma2(acc2, at, pack2(wh));
        }
        float h0, h1; unpack2(acc2, h0, h1);
        sm[O_HP + (2*ig    )*68 + d] = h0;
        sm[O_HP + (2*ig + 1)*68 + d] = h1;
    }
    __syncthreads();

    {
        int i = wid;
        float x0 = sm[O_HP + i*68 + lane];
        float x1 = sm[O_HP + i*68 + 32 + lane];
        float s1v = x0 + x1, s2v = x0*x0 + x1*x1;
#pragma unroll
        for (int o = 16; o; o >>= 1) {
            s1v += __shfl_xor_sync(0xffffffffu, s1v, o);
            s2v += __shfl_xor_sync(0xffffffffu, s2v, o);
        }
        float m   = s1v * (1.0f/64.0f);
        float var = s2v * (1.0f/64.0f) - m*m;
        float r   = rsqrtf(var + 1e-5f);
        size_t obase = ((size_t)(b*NN) + i0 + i)*FIN + head*HD;
        g_concat[obase + lane]      = (x0 - m)*r*ln_g[head*HD + lane]      + ln_b[head*HD + lane];
        g_concat[obase + 32 + lane] = (x1 - m)*r*ln_g[head*HD + 32 + lane] + ln_b[head*HD + 32 + lane];
    }
}

// ---------------------------------------------------------------------------
// Kernel 3: R9 version (unchanged).
// ---------------------------------------------------------------------------
__global__ __launch_bounds__(256) void k3_out(
    const float* __restrict__ hin, const float* __restrict__ Wo,
    const float* __restrict__ bo,  const float* __restrict__ g2,
    const float* __restrict__ b2,  float* __restrict__ out)
{
    const int NT = 8;
    int b  = blockIdx.x >> 5;
    int n0 = (blockIdx.x & 31) * NT;
    int tid = threadIdx.x;

    __shared__ __align__(16) float cst[FIN*12];
    __shared__ float hs2[NT][FIN];

#pragma unroll
    for (int nn = 0; nn < NT; ++nn) {
        cst[tid*12 + nn] = g_concat[((size_t)b*NN + n0 + nn)*FIN + tid];
        hs2[nn][tid]     = hin     [((size_t)b*NN + n0 + nn)*FIN + tid];
    }
    __syncthreads();

    float bv = bo[tid];
    float acc[NT];
#pragma unroll
    for (int nn = 0; nn < NT; ++nn) acc[nn] = bv;

#pragma unroll 4
    for (int f = 0; f < FIN; ++f) {
        float w = Wo[(size_t)f*FIN + tid];
        float4 cA = *reinterpret_cast<const float4*>(&cst[f*12]);
        float4 cB = *reinterpret_cast<const float4*>(&cst[f*12 + 4]);
        acc[0] = fmaf(cA.x, w, acc[0]); acc[1] = fmaf(cA.y, w, acc[1]);
        acc[2] = fmaf(cA.z, w, acc[2]); acc[3] = fmaf(cA.w, w, acc[3]);
        acc[4] = fmaf(cB.x, w, acc[4]); acc[5] = fmaf(cB.y, w, acc[5]);
        acc[6] = fmaf(cB.z, w, acc[6]); acc[7] = fmaf(cB.w, w, acc[7]);
    }
    __syncthreads();
#pragma unroll
    for (int nn = 0; nn < NT; ++nn)
        hs2[nn][tid] = acc[nn] + hs2[nn][tid];
    __syncthreads();

    int wid = tid >> 5, lane = tid & 31;
    float s1v = 0.f, s2v = 0.f;
#pragma unroll
    for (int k = 0; k < 8; ++k) {
        float x = hs2[wid][k*32 + lane];
        s1v += x; s2v += x*x;
    }
#pragma unroll
    for (int o = 16; o; o >>= 1) {
        s1v += __shfl_xor_sync(0xffffffffu, s1v, o);
        s2v += __shfl_xor_sync(0xffffffffu, s2v, o);
    }
    float m   = s1v * (1.0f/256.0f);
    float var = s2v * (1.0f/256.0f) - m*m;
    float rr  = rsqrtf(var + 1e-5f);
#pragma unroll
    for (int k = 0; k < 8; ++k) {
        int c = k*32 + lane;
        float x = hs2[wid][c];
        out[((size_t)b*NN + n0 + wid)*FIN + c] = (x - m)*rr*g2[c] + b2[c];
    }
}

// ---------------------------------------------------------------------------
extern "C" void kernel_launch(void* const* d_in, const int* in_sizes, int n_in,
                              void* d_out, int out_size)
{
    const float* h    = (const float*)d_in[0];
    const int*   adj  = (const int*)  d_in[1];
    const float* W    = (const float*)d_in[2];
    const float* We1  = (const float*)d_in[3];
    const float* be1  = (const float*)d_in[4];
    const float* Wa1  = (const float*)d_in[5];
    const float* ba1  = (const float*)d_in[6];
    const float* wa2  = (const float*)d_in[7];
    const float* ba2  = (const float*)d_in[8];
    const float* ln_g = (const float*)d_in[9];
    const float* ln_b = (const float*)d_in[10];
    const float* Wo   = (const float*)d_in[11];
    const float* bo   = (const float*)d_in[12];
    const float* g2   = (const float*)d_in[13];
    const float* b2   = (const float*)d_in[14];
    float* out = (float*)d_out;

    cudaFuncSetAttribute(k1_proj, cudaFuncAttributeMaxDynamicSharedMemorySize, K1_BYTES);
    cudaFuncSetAttribute(t2f,     cudaFuncAttributeMaxDynamicSharedMemorySize, T2_BYTES);

    k1_proj<<<NB*(NN/16), 256, K1_BYTES>>>(h, W, We1, be1, Wa1, ba1);
    t2f    <<<NB*NH*(NN/16), 512, T2_BYTES>>>(Wa1, wa2, adj, ba2, ln_g, ln_b);
    k3_out <<<NB*(NN/8), 256>>>(h, Wo, bo, g2, b2, out);
}

// round 11
// speedup vs baseline: 1.2679x; 1.1495x over previous
#include <cuda_runtime.h>
#include <math.h>
#include <stdint.h>

#define NB   8
#define NN   256
#define NH   4
#define HD   64
#define FIN  256
#define ALPHA 0.2f

// ---------------- scratch (__device__ globals; no allocs allowed) ----------
__device__ float g_Wh [NB*NH*NN*HD];
__device__ float g_si2[NB*NH*NN*HD];
__device__ float g_sj2[NB*NH*NN*HD];
__device__ float g_ei [NB*NH*NN*HD];
__device__ float g_ej [NB*NH*NN*HD];
__device__ float g_concat[NB*NN*FIN];

// ---------------- packed helpers -------------------------------------------
__device__ __forceinline__ uint32_t packbf(float lo, float hi) {
    uint32_t r;
    asm("cvt.rn.bf16x2.f32 %0, %1, %2;" : "=r"(r) : "f"(hi), "f"(lo));
    return r;
}
__device__ __forceinline__ uint32_t hadd2(uint32_t a, uint32_t b) {
    uint32_t r;
    asm("add.rn.bf16x2 %0, %1, %2;" : "=r"(r) : "r"(a), "r"(b));
    return r;
}
__device__ __forceinline__ uint32_t habs2(uint32_t a) { return a & 0x7FFF7FFFu; }

__device__ __forceinline__ void mma16816(float* c, uint32_t a0, uint32_t a1,
                                         uint32_t a2, uint32_t a3,
                                         uint32_t b0, uint32_t b1) {
    asm volatile("mma.sync.aligned.m16n8k16.row.col.f32.bf16.bf16.f32 "
                 "{%0,%1,%2,%3}, {%4,%5,%6,%7}, {%8,%9}, {%0,%1,%2,%3};"
                 : "+f"(c[0]), "+f"(c[1]), "+f"(c[2]), "+f"(c[3])
                 : "r"(a0), "r"(a1), "r"(a2), "r"(a3), "r"(b0), "r"(b1));
}
__device__ __forceinline__ uint32_t cvt_tf32(float x) {
    uint32_t r; asm("cvt.rna.tf32.f32 %0, %1;" : "=r"(r) : "f"(x)); return r;
}
__device__ __forceinline__ float cvt_tf32f(float x) {
    return __uint_as_float(cvt_tf32(x));
}
__device__ __forceinline__ void mma1688(float* c, uint32_t a0, uint32_t a1,
                                        uint32_t a2, uint32_t a3,
                                        uint32_t b0, uint32_t b1) {
    asm volatile("mma.sync.aligned.m16n8k8.row.col.f32.tf32.tf32.f32 "
                 "{%0,%1,%2,%3}, {%4,%5,%6,%7}, {%8,%9}, {%0,%1,%2,%3};"
                 : "+f"(c[0]), "+f"(c[1]), "+f"(c[2]), "+f"(c[3])
                 : "r"(a0), "r"(a1), "r"(a2), "r"(a3), "r"(b0), "r"(b1));
}

// ---------------------------------------------------------------------------
// Kernel 1 (tf32 tensor-core, unchanged from R10).
// ---------------------------------------------------------------------------
#define K1_HST 0
#define K1_TR  6144
#define K1_FLOATS (6144 + 4*3*64*24)
#define K1_BYTES  (K1_FLOATS*4)

__global__ __launch_bounds__(256) void k1_proj(
    const float* __restrict__ hin, const float* __restrict__ W,
    const float* __restrict__ We1, const float* __restrict__ be1,
    const float* __restrict__ Wa1, const float* __restrict__ ba1)
{
    extern __shared__ __align__(16) float s1[];
    int b  = blockIdx.x >> 4;
    int n0 = (blockIdx.x & 15) * 16;
    int tid = threadIdx.x;
    int wid = tid >> 5, lane = tid & 31;
    int gid = lane >> 2, tig = lane & 3;

    {
        const float* hrow = hin + ((size_t)b*NN + n0)*FIN + tid;
#pragma unroll
        for (int r = 0; r < 16; ++r)
            s1[K1_HST + tid*24 + r] = cvt_tf32f(hrow[(size_t)r*FIN]);
    }
    __syncthreads();

    const float* wp[12];
#pragma unroll
    for (int nt = 0; nt < 12; ++nt) {
        int ntg = wid*12 + nt;
        int mat = ntg >> 5, rem = ntg & 31;
        int head = rem >> 3, d0 = (rem & 7)*8;
        const float* base = (mat == 0)
            ? (W + (size_t)head*FIN*HD)
            : (We1 + (size_t)head*2*FIN*HD + (size_t)(mat-1)*FIN*HD);
        wp[nt] = base + d0 + gid;
    }

    float acc[12][4];
#pragma unroll
    for (int nt = 0; nt < 12; ++nt)
        acc[nt][0]=acc[nt][1]=acc[nt][2]=acc[nt][3]=0.f;

#pragma unroll 2
    for (int k0 = 0; k0 < FIN; k0 += 8) {
        uint32_t a0 = __float_as_uint(s1[K1_HST + (k0+tig)*24 + gid]);
        uint32_t a1 = __float_as_uint(s1[K1_HST + (k0+tig)*24 + gid + 8]);
        uint32_t a2 = __float_as_uint(s1[K1_HST + (k0+tig+4)*24 + gid]);
        uint32_t a3 = __float_as_uint(s1[K1_HST + (k0+tig+4)*24 + gid + 8]);
        int off0 = (k0+tig)*HD, off1 = (k0+tig+4)*HD;
#pragma unroll
        for (int nt = 0; nt < 12; ++nt) {
            uint32_t b0 = cvt_tf32(wp[nt][off0]);
            uint32_t b1 = cvt_tf32(wp[nt][off1]);
            mma1688(acc[nt], a0, a1, a2, a3, b0, b1);
        }
    }

#pragma unroll
    for (int nt = 0; nt < 12; ++nt) {
        int ntg = wid*12 + nt;
        int mat = ntg >> 5, rem = ntg & 31;
        int head = rem >> 3, d0 = (rem & 7)*8;
        int c0 = d0 + 2*tig;
        float v00 = acc[nt][0], v01 = acc[nt][1], v10 = acc[nt][2], v11 = acc[nt][3];
        if (mat == 1) {
            float e0 = be1[head*HD + c0], e1 = be1[head*HD + c0 + 1];
            v00 += e0; v01 += e1; v10 += e0; v11 += e1;
        }
        float* gout = (mat == 0) ? g_Wh : ((mat == 1) ? g_ei : g_ej);
        size_t rbase = ((size_t)(b*NH + head)*NN + n0);
        *reinterpret_cast<float2*>(&gout[(rbase + gid)*HD + c0])     = make_float2(v00, v01);
        *reinterpret_cast<float2*>(&gout[(rbase + gid + 8)*HD + c0]) = make_float2(v10, v11);
        int tb = K1_TR + (head*3 + mat)*64*24;
        s1[tb + (c0    )*24 + gid    ] = cvt_tf32f(v00);
        s1[tb + (c0 + 1)*24 + gid    ] = cvt_tf32f(v01);
        s1[tb + (c0    )*24 + gid + 8] = cvt_tf32f(v10);
        s1[tb + (c0 + 1)*24 + gid + 8] = cvt_tf32f(v11);
    }
    __syncthreads();

    {
        int head  = wid >> 1, which = wid & 1;
        int trb   = K1_TR + head*3*64*24;
        int hib   = trb + (which ? 1536 : 0);
        const float* wb_lo = Wa1 + ((size_t)head*3*HD + which*HD)*HD;
        const float* wb_hi = Wa1 + ((size_t)head*3*HD + 2*HD)*HD;

        float acc2[8][4];
#pragma unroll
        for (int nt = 0; nt < 8; ++nt)
            acc2[nt][0]=acc2[nt][1]=acc2[nt][2]=acc2[nt][3]=0.f;

#pragma unroll 2
        for (int ks = 0; ks < 8; ++ks) {
            int k0 = ks*8;
            uint32_t a0 = __float_as_uint(s1[trb + (k0+tig)*24 + gid]);
            uint32_t a1 = __float_as_uint(s1[trb + (k0+tig)*24 + gid + 8]);
            uint32_t a2 = __float_as_uint(s1[trb + (k0+tig+4)*24 + gid]);
            uint32_t a3 = __float_as_uint(s1[trb + (k0+tig+4)*24 + gid + 8]);
#pragma unroll
            for (int nt = 0; nt < 8; ++nt) {
                uint32_t b0 = cvt_tf32(wb_lo[(k0+tig)*HD + nt*8 + gid]);
                uint32_t b1 = cvt_tf32(wb_lo[(k0+tig+4)*HD + nt*8 + gid]);
                mma1688(acc2[nt], a0, a1, a2, a3, b0, b1);
            }
        }
#pragma unroll 2
        for (int ks = 0; ks < 8; ++ks) {
            int k0 = ks*8;
            uint32_t a0 = __float_as_uint(s1[hib + (k0+64+tig)*24 + gid]);
            uint32_t a1 = __float_as_uint(s1[hib + (k0+64+tig)*24 + gid + 8]);
            uint32_t a2 = __float_as_uint(s1[hib + (k0+64+tig+4)*24 + gid]);
            uint32_t a3 = __float_as_uint(s1[hib + (k0+64+tig+4)*24 + gid + 8]);
#pragma unroll
            for (int nt = 0; nt < 8; ++nt) {
                uint32_t b0 = cvt_tf32(0.6f * wb_hi[(k0+tig)*HD + nt*8 + gid]);
                uint32_t b1 = cvt_tf32(0.6f * wb_hi[(k0+tig+4)*HD + nt*8 + gid]);
                mma1688(acc2[nt], a0, a1, a2, a3, b0, b1);
            }
        }
#pragma unroll
        for (int nt = 0; nt < 8; ++nt) {
            int c0 = nt*8 + 2*tig;
            float v00=acc2[nt][0], v01=acc2[nt][1], v10=acc2[nt][2], v11=acc2[nt][3];
            if (which == 0) {
                float b0v = ba1[head*HD + c0], b1v = ba1[head*HD + c0 + 1];
                v00 += b0v; v01 += b1v; v10 += b0v; v11 += b1v;
            }
            float* gout = which == 0 ? g_si2 : g_sj2;
            size_t rbase = ((size_t)(b*NH + head)*NN + n0);
            *reinterpret_cast<float2*>(&gout[(rbase + gid)*HD + c0])     = make_float2(v00, v01);
            *reinterpret_cast<float2*>(&gout[(rbase + gid + 8)*HD + c0]) = make_float2(v10, v11);
        }
    }
}

// ---------------------------------------------------------------------------
// t2f: R7 256-thread / 2-CTA-per-SM version; hp phase upgraded to tf32 MMA.
// ---------------------------------------------------------------------------
#define O_EJ    0
#define O_WEBF  9216
#define O_EI    11264
#define O_SI    11776
#define O_WA2   12800
#define O_ET    12864
#define O_HP    17472
#define T2_FLOATS 18560
#define T2_BYTES  (T2_FLOATS*4)

__global__ __launch_bounds__(256, 2) void t2f(
    const float* __restrict__ Wa1, const float* __restrict__ wa2,
    const int*   __restrict__ adj, const float* __restrict__ ba2,
    const float* __restrict__ ln_g, const float* __restrict__ ln_b)
{
    extern __shared__ __align__(16) float sm[];
    uint32_t* smu = reinterpret_cast<uint32_t*>(sm);

    int bx   = blockIdx.x;
    int it   = bx & 15;
    int head = (bx >> 4) & 3;
    int b    = bx >> 6;
    int i0   = it * 16;
    int tid  = threadIdx.x;
    int wid  = tid >> 5, lane = tid & 31;
    int gid  = lane >> 2, tig = lane & 3;

    size_t bh = (size_t)(b*NH + head);
    const float* sj_base = g_sj2 + bh*NN*HD;
    const float* wh_base = g_Wh  + bh*NN*HD;

    // ---- staging ----
    for (int t = tid; t < NN*32; t += 256) {
        int j = t >> 5, kk = t & 31;
        float2 v = *reinterpret_cast<const float2*>(&g_ej[(bh*NN + j)*HD + 2*kk]);
        smu[O_EJ + j*36 + kk] = packbf(v.x, v.y);
    }
    for (int t = tid; t < 2048; t += 256) {
        int c   = t & 1;
        int ln2 = (t >> 1) & 31;
        int q   = t >> 6;
        int ks  = q >> 3, nt = q & 7;
        int tg  = ln2 & 3, gd = ln2 >> 2;
        int kk  = ks*8 + tg + (c ? 4 : 0);
        int d   = nt*8 + gd;
        float f0 = 0.4f * Wa1[((size_t)head*3*HD + 2*HD + 2*kk    )*HD + d];
        float f1 = 0.4f * Wa1[((size_t)head*3*HD + 2*HD + 2*kk + 1)*HD + d];
        smu[O_WEBF + t] = packbf(f0, f1);
    }
    for (int t = tid; t < 16*32; t += 256) {
        int ii = t >> 5, kk = t & 31;
        float2 v = *reinterpret_cast<const float2*>(&g_ei[(bh*NN + i0 + ii)*HD + 2*kk]);
        smu[O_EI + t] = packbf(v.x, v.y);
    }
    for (int t = tid; t < 16*64; t += 256) {
        int ii = t >> 6, d = t & 63;
        sm[O_SI + t] = g_si2[(bh*NN + i0 + ii)*HD + d];
    }
    if (tid < 64) sm[O_WA2 + tid] = wa2[head*HD + tid];
    __syncthreads();

    // ---- resident B fragments ----
    unsigned long long bfr[4][8];
#pragma unroll
    for (int ks = 0; ks < 4; ++ks)
#pragma unroll
        for (int nt = 0; nt < 8; ++nt)
            bfr[ks][nt] = *reinterpret_cast<const unsigned long long*>(
                &smu[O_WEBF + ((ks*8 + nt)*32 + lane)*2]);

    // ---- edge phase ----
    for (int ii = 0; ii < 16; ++ii) {
        uint32_t eir[8];
#pragma unroll
        for (int ks = 0; ks < 4; ++ks) {
            eir[2*ks]   = smu[O_EI + ii*32 + ks*8 + tig];
            eir[2*ks+1] = smu[O_EI + ii*32 + ks*8 + 4 + tig];
        }
#pragma unroll
        for (int p = 0; p < 2; ++p) {
            int j0 = (wid + 8*p) * 16;
            int r0 = j0 + gid, r1 = r0 + 8;

            float acc[8][4];
#pragma unroll
            for (int nt = 0; nt < 8; ++nt) {
                float2 s = *reinterpret_cast<const float2*>(&sm[O_SI + ii*64 + nt*8 + 2*tig]);
                acc[nt][0] = s.x; acc[nt][1] = s.y; acc[nt][2] = s.x; acc[nt][3] = s.y;
            }
#pragma unroll
            for (int ks = 0; ks < 4; ++ks) {
                uint32_t a0 = habs2(hadd2(smu[O_EJ + r0*36 + ks*8 + tig],     eir[2*ks]));
                uint32_t a1 = habs2(hadd2(smu[O_EJ + r1*36 + ks*8 + tig],     eir[2*ks]));
                uint32_t a2 = habs2(hadd2(smu[O_EJ + r0*36 + ks*8 + 4 + tig], eir[2*ks+1]));
                uint32_t a3 = habs2(hadd2(smu[O_EJ + r1*36 + ks*8 + 4 + tig], eir[2*ks+1]));
#pragma unroll
                for (int nt = 0; nt < 8; ++nt) {
                    uint32_t b0 = (uint32_t)(bfr[ks][nt] & 0xffffffffu);
                    uint32_t b1 = (uint32_t)(bfr[ks][nt] >> 32);
                    mma16816(acc[nt], a0, a1, a2, a3, b0, b1);
                }
            }
            float pe0 = 0.f, pe1 = 0.f;
#pragma unroll
            for (int nt = 0; nt < 8; ++nt) {
                int d = nt*8 + 2*tig;
                float2 sj0 = *reinterpret_cast<const float2*>(&sj_base[(size_t)r0*HD + d]);
                float2 sj1 = *reinterpret_cast<const float2*>(&sj_base[(size_t)r1*HD + d]);
                float2 w2  = *reinterpret_cast<const float2*>(&sm[O_WA2 + d]);
                float v00 = acc[nt][0] + sj0.x, v01 = acc[nt][1] + sj0.y;
                float v10 = acc[nt][2] + sj1.x, v11 = acc[nt][3] + sj1.y;
                pe0 = fmaf(fmaxf(v00, ALPHA*v00), w2.x, pe0);
                pe0 = fmaf(fmaxf(v01, ALPHA*v01), w2.y, pe0);
                pe1 = fmaf(fmaxf(v10, ALPHA*v10), w2.x, pe1);
                pe1 = fmaf(fmaxf(v11, ALPHA*v11), w2.y, pe1);
            }
            pe0 += __shfl_xor_sync(0xffffffffu, pe0, 1);
            pe0 += __shfl_xor_sync(0xffffffffu, pe0, 2);
            pe1 += __shfl_xor_sync(0xffffffffu, pe1, 1);
            pe1 += __shfl_xor_sync(0xffffffffu, pe1, 2);
            if (tig == 0) {
                sm[O_ET + r0*18 + ii] = pe0;
                sm[O_ET + r1*18 + ii] = pe1;
            }
        }
    }
    __syncthreads();

    // ---- masked softmax: warp handles i = 2*wid + r ----
    {
        float bav = ba2[head];
#pragma unroll
        for (int r = 0; r < 2; ++r) {
            int i = wid*2 + r;
            int iglob = i0 + i;
            float vals[8]; float mx = -1e30f;
#pragma unroll
            for (int s = 0; s < 8; ++s) {
                int j = lane + 32*s;
                float pe = sm[O_ET + j*18 + i] + bav;
                int a = adj[((size_t)b*NN + iglob)*NN + j];
                vals[s] = (a == 0) ? -1e9f : pe;
                mx = fmaxf(mx, vals[s]);
            }
#pragma unroll
            for (int o = 16; o; o >>= 1) mx = fmaxf(mx, __shfl_xor_sync(0xffffffffu, mx, o));
            float se = 0.f;
#pragma unroll
            for (int s = 0; s < 8; ++s) { vals[s] = __expf(vals[s] - mx); se += vals[s]; }
#pragma unroll
            for (int o = 16; o; o >>= 1) se += __shfl_xor_sync(0xffffffffu, se, o);
            float inv = 1.0f / se;
#pragma unroll
            for (int s = 0; s < 8; ++s)
                sm[O_ET + (lane + 32*s)*18 + i] = vals[s] * inv;
        }
    }
    __syncthreads();

    // ---- hp via tf32 MMA: warp wid owns d-chunk [wid*8, wid*8+8) ----
    {
        int n0w = wid * 8;
        float hacc[4] = {0.f, 0.f, 0.f, 0.f};
#pragma unroll 4
        for (int ks = 0; ks < 32; ++ks) {
            int k0 = ks*8;
            uint32_t a0 = cvt_tf32(sm[O_ET + (k0+tig)*18 + gid]);
            uint32_t a1 = cvt_tf32(sm[O_ET + (k0+tig)*18 + gid + 8]);
            uint32_t a2 = cvt_tf32(sm[O_ET + (k0+tig+4)*18 + gid]);
            uint32_t a3 = cvt_tf32(sm[O_ET + (k0+tig+4)*18 + gid + 8]);
            uint32_t b0 = cvt_tf32(wh_base[(size_t)(k0+tig)*HD + n0w + gid]);
            uint32_t b1 = cvt_tf32(wh_base[(size_t)(k0+tig+4)*HD + n0w + gid]);
            mma1688(hacc, a0, a1, a2, a3, b0, b1);
        }
        int c0 = n0w + 2*tig;
        sm[O_HP + gid*68 + c0]       = hacc[0];
        sm[O_HP + gid*68 + c0 + 1]   = hacc[1];
        sm[O_HP + (gid+8)*68 + c0]     = hacc[2];
        sm[O_HP + (gid+8)*68 + c0 + 1] = hacc[3];
    }
    __syncthreads();

    // ---- per-head layernorm: warp handles i = 2*wid + r ----
    {
#pragma unroll
        for (int r = 0; r < 2; ++r) {
            int i = wid*2 + r;
            float x0 = sm[O_HP + i*68 + lane];
            float x1 = sm[O_HP + i*68 + 32 + lane];
            float s1v = x0 + x1, s2v = x0*x0 + x1*x1;
#pragma unroll
            for (int o = 16; o; o >>= 1) {
                s1v += __shfl_xor_sync(0xffffffffu, s1v, o);
                s2v += __shfl_xor_sync(0xffffffffu, s2v, o);
            }
            float m   = s1v * (1.0f/64.0f);
            float var = s2v * (1.0f/64.0f) - m*m;
            float rr  = rsqrtf(var + 1e-5f);
            size_t obase = ((size_t)(b*NN) + i0 + i)*FIN + head*HD;
            g_concat[obase + lane]      = (x0 - m)*rr*ln_g[head*HD + lane]      + ln_b[head*HD + lane];
            g_concat[obase + 32 + lane] = (x1 - m)*rr*ln_g[head*HD + 32 + lane] + ln_b[head*HD + 32 + lane];
        }
    }
}

// ---------------------------------------------------------------------------
// Kernel 3: R9/R10 version (unchanged).
// ---------------------------------------------------------------------------
__global__ __launch_bounds__(256) void k3_out(
    const float* __restrict__ hin, const float* __restrict__ Wo,
    const float* __restrict__ bo,  const float* __restrict__ g2,
    const float* __restrict__ b2,  float* __restrict__ out)
{
    const int NT = 8;
    int b  = blockIdx.x >> 5;
    int n0 = (blockIdx.x & 31) * NT;
    int tid = threadIdx.x;

    __shared__ __align__(16) float cst[FIN*12];
    __shared__ float hs2[NT][FIN];

#pragma unroll
    for (int nn = 0; nn < NT; ++nn) {
        cst[tid*12 + nn] = g_concat[((size_t)b*NN + n0 + nn)*FIN + tid];
        hs2[nn][tid]     = hin     [((size_t)b*NN + n0 + nn)*FIN + tid];
    }
    __syncthreads();

    float bv = bo[tid];
    float acc[NT];
#pragma unroll
    for (int nn = 0; nn < NT; ++nn) acc[nn] = bv;

#pragma unroll 4
    for (int f = 0; f < FIN; ++f) {
        float w = Wo[(size_t)f*FIN + tid];
        float4 cA = *reinterpret_cast<const float4*>(&cst[f*12]);
        float4 cB = *reinterpret_cast<const float4*>(&cst[f*12 + 4]);
        acc[0] = fmaf(cA.x, w, acc[0]); acc[1] = fmaf(cA.y, w, acc[1]);
        acc[2] = fmaf(cA.z, w, acc[2]); acc[3] = fmaf(cA.w, w, acc[3]);
        acc[4] = fmaf(cB.x, w, acc[4]); acc[5] = fmaf(cB.y, w, acc[5]);
        acc[6] = fmaf(cB.z, w, acc[6]); acc[7] = fmaf(cB.w, w, acc[7]);
    }
    __syncthreads();
#pragma unroll
    for (int nn = 0; nn < NT; ++nn)
        hs2[nn][tid] = acc[nn] + hs2[nn][tid];
    __syncthreads();

    int wid = tid >> 5, lane = tid & 31;
    float s1v = 0.f, s2v = 0.f;
#pragma unroll
    for (int k = 0; k < 8; ++k) {
        float x = hs2[wid][k*32 + lane];
        s1v += x; s2v += x*x;
    }
#pragma unroll
    for (int o = 16; o; o >>= 1) {
        s1v += __shfl_xor_sync(0xffffffffu, s1v, o);
        s2v += __shfl_xor_sync(0xffffffffu, s2v, o);
    }
    float m   = s1v * (1.0f/256.0f);
    float var = s2v * (1.0f/256.0f) - m*m;
    float rr  = rsqrtf(var + 1e-5f);
#pragma unroll
    for (int k = 0; k < 8; ++k) {
        int c = k*32 + lane;
        float x = hs2[wid][c];
        out[((size_t)b*NN + n0 + wid)*FIN + c] = (x - m)*rr*g2[c] + b2[c];
    }
}

// ---------------------------------------------------------------------------
extern "C" void kernel_launch(void* const* d_in, const int* in_sizes, int n_in,
                              void* d_out, int out_size)
{
    const float* h    = (const float*)d_in[0];
    const int*   adj  = (const int*)  d_in[1];
    const float* W    = (const float*)d_in[2];
    const float* We1  = (const float*)d_in[3];
    const float* be1  = (const float*)d_in[4];
    const float* Wa1  = (const float*)d_in[5];
    const float* ba1  = (const float*)d_in[6];
    const float* wa2  = (const float*)d_in[7];
    const float* ba2  = (const float*)d_in[8];
    const float* ln_g = (const float*)d_in[9];
    const float* ln_b = (const float*)d_in[10];
    const float* Wo   = (const float*)d_in[11];
    const float* bo   = (const float*)d_in[12];
    const float* g2   = (const float*)d_in[13];
    const float* b2   = (const float*)d_in[14];
    float* out = (float*)d_out;

    cudaFuncSetAttribute(k1_proj, cudaFuncAttributeMaxDynamicSharedMemorySize, K1_BYTES);
    cudaFuncSetAttribute(t2f,     cudaFuncAttributeMaxDynamicSharedMemorySize, T2_BYTES);

    k1_proj<<<NB*(NN/16), 256, K1_BYTES>>>(h, W, We1, be1, Wa1, ba1);
    t2f    <<<NB*NH*(NN/16), 256, T2_BYTES>>>(Wa1, wa2, adj, ba2, ln_g, ln_b);
    k3_out <<<NB*(NN/8), 256>>>(h, Wo, bo, g2, b2, out);
}